// round 1
// baseline (speedup 1.0000x reference)
#include <cuda_runtime.h>
#include <math.h>

// Problem constants (fixed by the reference)
#define C_DIM   1024
#define T_SEQ   2048
#define BATCH   8
#define M_TOTAL (BATCH * T_SEQ)   // 16384

// Tiling
#define BM 128
#define BN 128
#define BK 16
#define TM 8
#define TN 8

// ---------------- scratch (static device globals; no allocation) ----------------
__device__ float g_h[(size_t)M_TOTAL * C_DIM];            // 64 MiB (reused q/k/v)
__device__ float g_q[(size_t)M_TOTAL * C_DIM];            // 64 MiB
__device__ float g_k[(size_t)M_TOTAL * C_DIM];            // 64 MiB
__device__ float g_v[(size_t)M_TOTAL * C_DIM];            // 64 MiB
__device__ float g_s[(size_t)BATCH * T_SEQ * T_SEQ];      // 128 MiB
__device__ float g_o[(size_t)M_TOTAL * C_DIM];            // 64 MiB

__device__ __forceinline__ float gelu_exact(float x) {
    // torch nn.GELU default / jax approximate=False: 0.5*x*(1+erf(x/sqrt(2)))
    return 0.5f * x * (1.0f + erff(x * 0.70710678118654752440f));
}

// =====================================================================
// GEMM: C[m,n] = act( sum_k A[m,k]*B[k,n] + bias[n] )
// A: [M,K] row-major, B: [K,N] row-major. All dims multiples of tile sizes.
// =====================================================================
template <int ACT>
__global__ __launch_bounds__(256, 2) void sgemm_bias_kernel(
    const float* __restrict__ A, const float* __restrict__ B,
    const float* __restrict__ bias, float* __restrict__ Cout,
    int N, int K)
{
    __shared__ float As[BK][BM];
    __shared__ float Bs[BK][BN];
    const int tid = threadIdx.x;
    const int bm = blockIdx.y * BM;
    const int bn = blockIdx.x * BN;
    const int tr = (tid >> 4) * TM;
    const int tc = (tid & 15) * TN;

    float acc[TM][TN];
    #pragma unroll
    for (int i = 0; i < TM; i++)
        #pragma unroll
        for (int j = 0; j < TN; j++) acc[i][j] = 0.0f;

    for (int k0 = 0; k0 < K; k0 += BK) {
        #pragma unroll
        for (int l = 0; l < 2; l++) {
            int s = tid + l * 256;
            int ar = s >> 2, ac = (s & 3) << 2;          // 128 rows x 16 cols of A
            float4 av = *reinterpret_cast<const float4*>(&A[(size_t)(bm + ar) * K + k0 + ac]);
            As[ac + 0][ar] = av.x; As[ac + 1][ar] = av.y;
            As[ac + 2][ar] = av.z; As[ac + 3][ar] = av.w;
            int br = s >> 5, bc = (s & 31) << 2;         // 16 rows x 128 cols of B
            *reinterpret_cast<float4*>(&Bs[br][bc]) =
                *reinterpret_cast<const float4*>(&B[(size_t)(k0 + br) * N + bn + bc]);
        }
        __syncthreads();
        #pragma unroll
        for (int kk = 0; kk < BK; kk++) {
            float a_[TM], b_[TN];
            #pragma unroll
            for (int i = 0; i < TM; i += 4)
                *reinterpret_cast<float4*>(&a_[i]) =
                    *reinterpret_cast<const float4*>(&As[kk][tr + i]);
            #pragma unroll
            for (int j = 0; j < TN; j += 4)
                *reinterpret_cast<float4*>(&b_[j]) =
                    *reinterpret_cast<const float4*>(&Bs[kk][tc + j]);
            #pragma unroll
            for (int i = 0; i < TM; i++)
                #pragma unroll
                for (int j = 0; j < TN; j++)
                    acc[i][j] = fmaf(a_[i], b_[j], acc[i][j]);
        }
        __syncthreads();
    }

    #pragma unroll
    for (int i = 0; i < TM; i++) {
        const size_t row = (size_t)(bm + tr + i);
        #pragma unroll
        for (int j = 0; j < TN; j += 4) {
            float4 o;
            o.x = acc[i][j + 0] + bias[bn + tc + j + 0];
            o.y = acc[i][j + 1] + bias[bn + tc + j + 1];
            o.z = acc[i][j + 2] + bias[bn + tc + j + 2];
            o.w = acc[i][j + 3] + bias[bn + tc + j + 3];
            if (ACT) {
                o.x = gelu_exact(o.x); o.y = gelu_exact(o.y);
                o.z = gelu_exact(o.z); o.w = gelu_exact(o.w);
            }
            *reinterpret_cast<float4*>(&Cout[row * N + bn + tc + j]) = o;
        }
    }
}

// =====================================================================
// scores[b,i,j] = (i>=j) ? dot(q[b,i,:], k[b,j,:]) * inv_scale : 0
// Only lower-triangular blocks computed; upper blocks never read downstream.
// =====================================================================
__global__ __launch_bounds__(256, 2) void scores_kernel(
    const float* __restrict__ Q, const float* __restrict__ Kmat,
    float* __restrict__ S, float inv_scale)
{
    if (blockIdx.x > blockIdx.y) return;   // strictly upper block-triangle: skip
    const int b = blockIdx.z;
    const float* A  = Q    + (size_t)b * T_SEQ * C_DIM;
    const float* Bk = Kmat + (size_t)b * T_SEQ * C_DIM;
    float*       Sb = S    + (size_t)b * T_SEQ * T_SEQ;

    __shared__ float As[BK][BM];
    __shared__ float Bs[BK][BN];
    const int tid = threadIdx.x;
    const int bm = blockIdx.y * BM;
    const int bn = blockIdx.x * BN;
    const int tr = (tid >> 4) * TM;
    const int tc = (tid & 15) * TN;

    float acc[TM][TN];
    #pragma unroll
    for (int i = 0; i < TM; i++)
        #pragma unroll
        for (int j = 0; j < TN; j++) acc[i][j] = 0.0f;

    for (int k0 = 0; k0 < C_DIM; k0 += BK) {
        #pragma unroll
        for (int l = 0; l < 2; l++) {
            int s = tid + l * 256;
            int r = s >> 2, c = (s & 3) << 2;   // 128 rows x 16 k, both operands
            float4 av = *reinterpret_cast<const float4*>(&A[(size_t)(bm + r) * C_DIM + k0 + c]);
            As[c + 0][r] = av.x; As[c + 1][r] = av.y;
            As[c + 2][r] = av.z; As[c + 3][r] = av.w;
            float4 bv = *reinterpret_cast<const float4*>(&Bk[(size_t)(bn + r) * C_DIM + k0 + c]);
            Bs[c + 0][r] = bv.x; Bs[c + 1][r] = bv.y;
            Bs[c + 2][r] = bv.z; Bs[c + 3][r] = bv.w;
        }
        __syncthreads();
        #pragma unroll
        for (int kk = 0; kk < BK; kk++) {
            float a_[TM], b_[TN];
            #pragma unroll
            for (int i = 0; i < TM; i += 4)
                *reinterpret_cast<float4*>(&a_[i]) =
                    *reinterpret_cast<const float4*>(&As[kk][tr + i]);
            #pragma unroll
            for (int j = 0; j < TN; j += 4)
                *reinterpret_cast<float4*>(&b_[j]) =
                    *reinterpret_cast<const float4*>(&Bs[kk][tc + j]);
            #pragma unroll
            for (int i = 0; i < TM; i++)
                #pragma unroll
                for (int j = 0; j < TN; j++)
                    acc[i][j] = fmaf(a_[i], b_[j], acc[i][j]);
        }
        __syncthreads();
    }

    #pragma unroll
    for (int i = 0; i < TM; i++) {
        const int gi = bm + tr + i;
        #pragma unroll
        for (int j = 0; j < TN; j += 4) {
            float4 o;
            const int gj = bn + tc + j;
            o.x = (gi >= gj + 0) ? acc[i][j + 0] * inv_scale : 0.0f;
            o.y = (gi >= gj + 1) ? acc[i][j + 1] * inv_scale : 0.0f;
            o.z = (gi >= gj + 2) ? acc[i][j + 2] * inv_scale : 0.0f;
            o.w = (gi >= gj + 3) ? acc[i][j + 3] * inv_scale : 0.0f;
            *reinterpret_cast<float4*>(&Sb[(size_t)gi * T_SEQ + gj]) = o;
        }
    }
}

// =====================================================================
// out[b,i,:] = sum_{j<=i} scores[b,i,j] * v[b,j,:]
// Causal: K-loop for row block [bm, bm+BM) stops at bm+BM.
// =====================================================================
__global__ __launch_bounds__(256, 2) void att_out_kernel(
    const float* __restrict__ S, const float* __restrict__ V,
    float* __restrict__ O)
{
    const int b = blockIdx.z;
    const float* A  = S + (size_t)b * T_SEQ * T_SEQ;   // [T,T]
    const float* Bv = V + (size_t)b * T_SEQ * C_DIM;   // [T,C]
    float*       Ob = O + (size_t)b * T_SEQ * C_DIM;

    __shared__ float As[BK][BM];
    __shared__ float Bs[BK][BN];
    const int tid = threadIdx.x;
    const int bm = blockIdx.y * BM;
    const int bn = blockIdx.x * BN;
    const int tr = (tid >> 4) * TM;
    const int tc = (tid & 15) * TN;
    const int kend = bm + BM;                  // causal K limit

    float acc[TM][TN];
    #pragma unroll
    for (int i = 0; i < TM; i++)
        #pragma unroll
        for (int j = 0; j < TN; j++) acc[i][j] = 0.0f;

    for (int k0 = 0; k0 < kend; k0 += BK) {
        #pragma unroll
        for (int l = 0; l < 2; l++) {
            int s = tid + l * 256;
            int ar = s >> 2, ac = (s & 3) << 2;
            float4 av = *reinterpret_cast<const float4*>(&A[(size_t)(bm + ar) * T_SEQ + k0 + ac]);
            As[ac + 0][ar] = av.x; As[ac + 1][ar] = av.y;
            As[ac + 2][ar] = av.z; As[ac + 3][ar] = av.w;
            int br = s >> 5, bc = (s & 31) << 2;
            *reinterpret_cast<float4*>(&Bs[br][bc]) =
                *reinterpret_cast<const float4*>(&Bv[(size_t)(k0 + br) * C_DIM + bn + bc]);
        }
        __syncthreads();
        #pragma unroll
        for (int kk = 0; kk < BK; kk++) {
            float a_[TM], b_[TN];
            #pragma unroll
            for (int i = 0; i < TM; i += 4)
                *reinterpret_cast<float4*>(&a_[i]) =
                    *reinterpret_cast<const float4*>(&As[kk][tr + i]);
            #pragma unroll
            for (int j = 0; j < TN; j += 4)
                *reinterpret_cast<float4*>(&b_[j]) =
                    *reinterpret_cast<const float4*>(&Bs[kk][tc + j]);
            #pragma unroll
            for (int i = 0; i < TM; i++)
                #pragma unroll
                for (int j = 0; j < TN; j++)
                    acc[i][j] = fmaf(a_[i], b_[j], acc[i][j]);
        }
        __syncthreads();
    }

    #pragma unroll
    for (int i = 0; i < TM; i++) {
        const size_t row = (size_t)(bm + tr + i);
        #pragma unroll
        for (int j = 0; j < TN; j += 4) {
            float4 o;
            o.x = acc[i][j + 0]; o.y = acc[i][j + 1];
            o.z = acc[i][j + 2]; o.w = acc[i][j + 3];
            *reinterpret_cast<float4*>(&Ob[row * C_DIM + bn + tc + j]) = o;
        }
    }
}

// =====================================================================
// LayerNorm over last dim (C=1024), weight+bias, eps=1e-5
// One block per row, 256 threads, one float4 per thread.
// =====================================================================
__global__ __launch_bounds__(256) void layernorm_kernel(
    const float* __restrict__ X, const float* __restrict__ w,
    const float* __restrict__ bia, float* __restrict__ out)
{
    const int row = blockIdx.x;
    const int tid = threadIdx.x;
    const float* xr = X + (size_t)row * C_DIM;

    float4 v = *reinterpret_cast<const float4*>(&xr[tid * 4]);
    float s  = v.x + v.y + v.z + v.w;
    float sq = v.x * v.x + v.y * v.y + v.z * v.z + v.w * v.w;

    #pragma unroll
    for (int off = 16; off > 0; off >>= 1) {
        s  += __shfl_xor_sync(0xffffffffu, s,  off);
        sq += __shfl_xor_sync(0xffffffffu, sq, off);
    }
    __shared__ float red_s[8], red_q[8];
    const int wid = tid >> 5;
    if ((tid & 31) == 0) { red_s[wid] = s; red_q[wid] = sq; }
    __syncthreads();
    __shared__ float mu_s, inv_s;
    if (tid == 0) {
        float ts = 0.f, tq = 0.f;
        #pragma unroll
        for (int i = 0; i < 8; i++) { ts += red_s[i]; tq += red_q[i]; }
        float mu  = ts * (1.0f / C_DIM);
        float var = tq * (1.0f / C_DIM) - mu * mu;
        mu_s  = mu;
        inv_s = rsqrtf(var + 1e-5f);
    }
    __syncthreads();
    const float mu = mu_s, inv = inv_s;

    float4 wv = *reinterpret_cast<const float4*>(&w[tid * 4]);
    float4 bv = *reinterpret_cast<const float4*>(&bia[tid * 4]);
    float4 o;
    o.x = (v.x - mu) * inv * wv.x + bv.x;
    o.y = (v.y - mu) * inv * wv.y + bv.y;
    o.z = (v.z - mu) * inv * wv.z + bv.z;
    o.w = (v.w - mu) * inv * wv.w + bv.w;
    *reinterpret_cast<float4*>(&out[(size_t)row * C_DIM + tid * 4]) = o;
}

// =====================================================================
// Launch (graph-capturable: kernel launches only)
// =====================================================================
extern "C" void kernel_launch(void* const* d_in, const int* in_sizes, int n_in,
                              void* d_out, int out_size)
{
    (void)in_sizes; (void)n_in; (void)out_size;
    const float* x    = (const float*)d_in[0];
    const float* W1q  = (const float*)d_in[1];
    const float* b1q  = (const float*)d_in[2];
    const float* W2q  = (const float*)d_in[3];
    const float* b2q  = (const float*)d_in[4];
    const float* W1k  = (const float*)d_in[5];
    const float* b1k  = (const float*)d_in[6];
    const float* W2k  = (const float*)d_in[7];
    const float* b2k  = (const float*)d_in[8];
    const float* W1v  = (const float*)d_in[9];
    const float* b1v  = (const float*)d_in[10];
    const float* W2v  = (const float*)d_in[11];
    const float* b2v  = (const float*)d_in[12];
    const float* ln_w = (const float*)d_in[13];
    const float* ln_b = (const float*)d_in[14];
    float* out = (float*)d_out;

    float *h, *q, *k, *v, *s, *o;
    cudaGetSymbolAddress((void**)&h, g_h);
    cudaGetSymbolAddress((void**)&q, g_q);
    cudaGetSymbolAddress((void**)&k, g_k);
    cudaGetSymbolAddress((void**)&v, g_v);
    cudaGetSymbolAddress((void**)&s, g_s);
    cudaGetSymbolAddress((void**)&o, g_o);

    const float inv_scale = 1.0f / sqrtf((float)C_DIM * (float)T_SEQ);

    dim3 blk(256);
    dim3 g_mlp(C_DIM / BN, M_TOTAL / BM);          // (8, 128)

    // q = MLP_q(x), k = MLP_k(x), v = MLP_v(x)   (g_h reused as hidden buffer)
    sgemm_bias_kernel<1><<<g_mlp, blk>>>(x, W1q, b1q, h, C_DIM, C_DIM);
    sgemm_bias_kernel<0><<<g_mlp, blk>>>(h, W2q, b2q, q, C_DIM, C_DIM);
    sgemm_bias_kernel<1><<<g_mlp, blk>>>(x, W1k, b1k, h, C_DIM, C_DIM);
    sgemm_bias_kernel<0><<<g_mlp, blk>>>(h, W2k, b2k, k, C_DIM, C_DIM);
    sgemm_bias_kernel<1><<<g_mlp, blk>>>(x, W1v, b1v, h, C_DIM, C_DIM);
    sgemm_bias_kernel<0><<<g_mlp, blk>>>(h, W2v, b2v, v, C_DIM, C_DIM);

    dim3 g_sc(T_SEQ / BN, T_SEQ / BM, BATCH);      // (16, 16, 8)
    scores_kernel<<<g_sc, blk>>>(q, k, s, inv_scale);

    dim3 g_at(C_DIM / BN, T_SEQ / BM, BATCH);      // (8, 16, 8)
    att_out_kernel<<<g_at, blk>>>(s, v, o);

    layernorm_kernel<<<M_TOTAL, 256>>>(o, ln_w, ln_b, out);
}

// round 4
// speedup vs baseline: 1.7424x; 1.7424x over previous
#include <cuda_runtime.h>
#include <cuda_bf16.h>
#include <math.h>
#include <stdint.h>

// ---------------- problem constants ----------------
#define C_DIM   1024
#define T_SEQ   2048
#define BATCH   8
#define M_TOTAL (BATCH * T_SEQ)       // 16384

// ---------------- tile config ----------------
#define BM 128
#define BN 128
#define BKF 32                         // fp32 k-values per chunk
#define ROWB 80                        // smem bytes per row: 32 bf16 (64B) + 16B pad
#define TILEB (128 * ROWB)             // 10240 B per (operand, half)
#define AH_OFF 0
#define AL_OFF (1 * TILEB)
#define BH_OFF (2 * TILEB)
#define BL_OFF (3 * TILEB)
#define STAGEB (4 * TILEB)             // 40960 B per stage
#define SMEMB  (2 * STAGEB)            // 81920 B total

// ---------------- scratch ----------------
__device__ float g_h  [(size_t)3 * M_TOTAL * C_DIM];
__device__ float g_qkv[(size_t)3 * M_TOTAL * C_DIM];
__device__ float g_s  [(size_t)BATCH * T_SEQ * T_SEQ];
__device__ float g_o  [(size_t)M_TOTAL * C_DIM];
__device__ float g_vt [(size_t)BATCH * C_DIM * T_SEQ];
__device__ float g_wt [(size_t)6 * C_DIM * C_DIM];

// ---------------- helpers ----------------
__device__ __forceinline__ uint32_t smem_u32(const void* p) {
    uint32_t a;
    asm("{ .reg .u64 t; cvta.to.shared.u64 t, %1; cvt.u32.u64 %0, t; }" : "=r"(a) : "l"(p));
    return a;
}
__device__ __forceinline__ void ldsm4(uint32_t* r, uint32_t addr) {
    asm volatile("ldmatrix.sync.aligned.m8n8.x4.shared.b16 {%0,%1,%2,%3}, [%4];"
                 : "=r"(r[0]), "=r"(r[1]), "=r"(r[2]), "=r"(r[3]) : "r"(addr));
}
__device__ __forceinline__ void mma16816(float* c, const uint32_t* a, uint32_t b0, uint32_t b1) {
    asm volatile("mma.sync.aligned.m16n8k16.row.col.f32.bf16.bf16.f32 "
                 "{%0,%1,%2,%3}, {%4,%5,%6,%7}, {%8,%9}, {%0,%1,%2,%3};"
                 : "+f"(c[0]), "+f"(c[1]), "+f"(c[2]), "+f"(c[3])
                 : "r"(a[0]), "r"(a[1]), "r"(a[2]), "r"(a[3]), "r"(b0), "r"(b1));
}
__device__ __forceinline__ float gelu_exact(float x) {
    return 0.5f * x * (1.0f + erff(x * 0.70710678118654752440f));
}
// split float4 -> packed bf16x2 hi pair + lo pair
__device__ __forceinline__ void split4(float4 v, uint2& hi, uint2& lo) {
    __nv_bfloat162 h01 = __floats2bfloat162_rn(v.x, v.y);
    __nv_bfloat162 h23 = __floats2bfloat162_rn(v.z, v.w);
    float lx = v.x - __bfloat162float(h01.x);
    float ly = v.y - __bfloat162float(h01.y);
    float lz = v.z - __bfloat162float(h23.x);
    float lw = v.w - __bfloat162float(h23.y);
    __nv_bfloat162 l01 = __floats2bfloat162_rn(lx, ly);
    __nv_bfloat162 l23 = __floats2bfloat162_rn(lz, lw);
    hi = make_uint2(*reinterpret_cast<uint32_t*>(&h01), *reinterpret_cast<uint32_t*>(&h23));
    lo = make_uint2(*reinterpret_cast<uint32_t*>(&l01), *reinterpret_cast<uint32_t*>(&l23));
}

// =====================================================================
// bf16x3 tensor-core GEMM:  C[m,n] = epi( sum_k A[m,k] * B[n,k] )
//   A: [rows, lda] K-contiguous; B: [cols, ldb] K-contiguous
//   EPI: 0 bias+GELU, 1 bias, 2 causal mask*scale, 3 plain
//   SKIP: skip CTA if bn > bm+127 (scores upper triangle)
//   CK:   K limit = bm+128 (att causal)
// =====================================================================
template <int EPI, bool SKIP, bool CK>
__global__ __launch_bounds__(256, 1)
void mma_gemm(const float* __restrict__ A, const float* __restrict__ B,
              const float* __restrict__ b0, const float* __restrict__ b1,
              const float* __restrict__ b2, float* __restrict__ Cout,
              int lda, int ldb, int ldc, int kdim,
              long long sA, long long sB, long long sC, float scale)
{
    const int bm = blockIdx.y * BM;
    const int bn = blockIdx.x * BN;
    if (SKIP && bn > bm + (BM - 1)) return;
    const int z = blockIdx.z;
    A += (size_t)z * sA; B += (size_t)z * sB; Cout += (size_t)z * sC;
    const float* bias = (z == 0) ? b0 : ((z == 1) ? b1 : b2);

    extern __shared__ __align__(128) char smem[];
    const uint32_t sb = smem_u32(smem);
    const int tid = threadIdx.x, lane = tid & 31, wid = tid >> 5;
    const int wm = (wid >> 1) * 32;          // warp m offset (4 rows of warps)
    const int wn = (wid & 1) * 64;           // warp n offset (2 cols of warps)

    const int kend = CK ? (bm + BM) : kdim;
    const int NC = kend / BKF;

    // global-load segment mapping: 1024 float4 segs per operand, 4 per thread
    int r_[4], k_[4];
    #pragma unroll
    for (int i = 0; i < 4; i++) { int s = tid + i * 256; r_[i] = s >> 3; k_[i] = s & 7; }

    float4 ra[4], rb[4];
    auto do_ldg = [&](int c) {
        const int k0 = c * BKF;
        #pragma unroll
        for (int i = 0; i < 4; i++) {
            ra[i] = *reinterpret_cast<const float4*>(A + (size_t)(bm + r_[i]) * lda + k0 + k_[i] * 4);
            rb[i] = *reinterpret_cast<const float4*>(B + (size_t)(bn + r_[i]) * ldb + k0 + k_[i] * 4);
        }
    };
    auto do_sts = [&](uint32_t stg) {
        #pragma unroll
        for (int i = 0; i < 4; i++) {
            const uint32_t off = stg + (uint32_t)r_[i] * ROWB + (uint32_t)k_[i] * 8;
            uint2 hi, lo;
            split4(ra[i], hi, lo);
            *reinterpret_cast<uint2*>(smem + off + AH_OFF) = hi;
            *reinterpret_cast<uint2*>(smem + off + AL_OFF) = lo;
            split4(rb[i], hi, lo);
            *reinterpret_cast<uint2*>(smem + off + BH_OFF) = hi;
            *reinterpret_cast<uint2*>(smem + off + BL_OFF) = lo;
        }
    };

    float acc[2][8][4];
    #pragma unroll
    for (int mt = 0; mt < 2; mt++)
        #pragma unroll
        for (int nt = 0; nt < 8; nt++)
            #pragma unroll
            for (int e = 0; e < 4; e++) acc[mt][nt][e] = 0.0f;

    // ldmatrix lane addressing
    const uint32_t lrow = lane & 15;
    const uint32_t lcol = (uint32_t)(lane >> 4) * 16;

    do_ldg(0);
    do_sts(0);
    __syncthreads();

    for (int c = 0; c < NC; c++) {
        const uint32_t stg = (uint32_t)(c & 1) * STAGEB;
        if (c + 1 < NC) do_ldg(c + 1);

        #pragma unroll
        for (int s = 0; s < 2; s++) {
            uint32_t ah[2][4], al[2][4], bh[4][4], bl[4][4];
            #pragma unroll
            for (int mt = 0; mt < 2; mt++) {
                uint32_t ad = sb + stg + (uint32_t)(wm + mt * 16 + lrow) * ROWB + s * 32 + lcol;
                ldsm4(ah[mt], ad + AH_OFF);
                ldsm4(al[mt], ad + AL_OFF);
            }
            #pragma unroll
            for (int ng = 0; ng < 4; ng++) {
                uint32_t bd = sb + stg + (uint32_t)(wn + ng * 16 + lrow) * ROWB + s * 32 + lcol;
                ldsm4(bh[ng], bd + BH_OFF);
                ldsm4(bl[ng], bd + BL_OFF);
            }
            #pragma unroll
            for (int mt = 0; mt < 2; mt++) {
                #pragma unroll
                for (int ng = 0; ng < 4; ng++) {
                    // n-tile 2*ng   : B regs {r0, r2}  (rows wn+ng*16+0..7)
                    mma16816(acc[mt][2 * ng],     ah[mt], bh[ng][0], bh[ng][2]);
                    mma16816(acc[mt][2 * ng],     ah[mt], bl[ng][0], bl[ng][2]);
                    mma16816(acc[mt][2 * ng],     al[mt], bh[ng][0], bh[ng][2]);
                    // n-tile 2*ng+1 : B regs {r1, r3}  (rows wn+ng*16+8..15)
                    mma16816(acc[mt][2 * ng + 1], ah[mt], bh[ng][1], bh[ng][3]);
                    mma16816(acc[mt][2 * ng + 1], ah[mt], bl[ng][1], bl[ng][3]);
                    mma16816(acc[mt][2 * ng + 1], al[mt], bh[ng][1], bh[ng][3]);
                }
            }
        }

        if (c + 1 < NC) {
            do_sts((uint32_t)((c + 1) & 1) * STAGEB);
            __syncthreads();
        }
    }

    // ---- epilogue: direct fragment stores (float2 per row-pair) ----
    const int erow = lane >> 2;
    const int ecol = (lane & 3) * 2;
    #pragma unroll
    for (int mt = 0; mt < 2; mt++) {
        #pragma unroll
        for (int nt = 0; nt < 8; nt++) {
            const int gr = bm + wm + mt * 16 + erow;
            const int gc = bn + wn + nt * 8 + ecol;
            float v0 = acc[mt][nt][0], v1 = acc[mt][nt][1];
            float v2 = acc[mt][nt][2], v3 = acc[mt][nt][3];
            if (EPI == 0) {
                const float bb0 = bias[gc], bb1 = bias[gc + 1];
                v0 = gelu_exact(v0 + bb0); v1 = gelu_exact(v1 + bb1);
                v2 = gelu_exact(v2 + bb0); v3 = gelu_exact(v3 + bb1);
            } else if (EPI == 1) {
                const float bb0 = bias[gc], bb1 = bias[gc + 1];
                v0 += bb0; v1 += bb1; v2 += bb0; v3 += bb1;
            } else if (EPI == 2) {
                v0 = (gr     >= gc    ) ? v0 * scale : 0.0f;
                v1 = (gr     >= gc + 1) ? v1 * scale : 0.0f;
                v2 = (gr + 8 >= gc    ) ? v2 * scale : 0.0f;
                v3 = (gr + 8 >= gc + 1) ? v3 * scale : 0.0f;
            }
            *reinterpret_cast<float2*>(Cout + (size_t)gr * ldc + gc)       = make_float2(v0, v1);
            *reinterpret_cast<float2*>(Cout + (size_t)(gr + 8) * ldc + gc) = make_float2(v2, v3);
        }
    }
}

// =====================================================================
// 32x32 tiled transpose: out[c, r] = in[r, c], batched over z
// =====================================================================
__global__ __launch_bounds__(256) void transpose_kernel(
    const float* __restrict__ in, float* __restrict__ out,
    int R, int Cc, long long sin, long long sout)
{
    __shared__ float t[32][33];
    const float* ib = in + (size_t)blockIdx.z * sin;
    float* ob = out + (size_t)blockIdx.z * sout;
    const int c0 = blockIdx.x * 32, r0 = blockIdx.y * 32;
    const int tx = threadIdx.x, ty = threadIdx.y;
    #pragma unroll
    for (int i = ty; i < 32; i += 8)
        t[i][tx] = ib[(size_t)(r0 + i) * Cc + c0 + tx];
    __syncthreads();
    #pragma unroll
    for (int i = ty; i < 32; i += 8)
        ob[(size_t)(c0 + i) * R + r0 + tx] = t[tx][i];
}

// =====================================================================
// LayerNorm over last dim (C=1024), weight+bias, eps=1e-5
// =====================================================================
__global__ __launch_bounds__(256) void layernorm_kernel(
    const float* __restrict__ X, const float* __restrict__ w,
    const float* __restrict__ bia, float* __restrict__ out)
{
    const int row = blockIdx.x;
    const int tid = threadIdx.x;
    const float* xr = X + (size_t)row * C_DIM;

    float4 v = *reinterpret_cast<const float4*>(&xr[tid * 4]);
    float s  = v.x + v.y + v.z + v.w;
    float sq = v.x * v.x + v.y * v.y + v.z * v.z + v.w * v.w;
    #pragma unroll
    for (int off = 16; off > 0; off >>= 1) {
        s  += __shfl_xor_sync(0xffffffffu, s,  off);
        sq += __shfl_xor_sync(0xffffffffu, sq, off);
    }
    __shared__ float red_s[8], red_q[8];
    const int wid = tid >> 5;
    if ((tid & 31) == 0) { red_s[wid] = s; red_q[wid] = sq; }
    __syncthreads();
    __shared__ float mu_s, inv_s;
    if (tid == 0) {
        float ts = 0.f, tq = 0.f;
        #pragma unroll
        for (int i = 0; i < 8; i++) { ts += red_s[i]; tq += red_q[i]; }
        float mu  = ts * (1.0f / C_DIM);
        float var = tq * (1.0f / C_DIM) - mu * mu;
        mu_s = mu; inv_s = rsqrtf(var + 1e-5f);
    }
    __syncthreads();
    const float mu = mu_s, inv = inv_s;
    float4 wv = *reinterpret_cast<const float4*>(&w[tid * 4]);
    float4 bv = *reinterpret_cast<const float4*>(&bia[tid * 4]);
    float4 o;
    o.x = (v.x - mu) * inv * wv.x + bv.x;
    o.y = (v.y - mu) * inv * wv.y + bv.y;
    o.z = (v.z - mu) * inv * wv.z + bv.z;
    o.w = (v.w - mu) * inv * wv.w + bv.w;
    *reinterpret_cast<float4*>(&out[(size_t)row * C_DIM + tid * 4]) = o;
}

// =====================================================================
// launch
// =====================================================================
extern "C" void kernel_launch(void* const* d_in, const int* in_sizes, int n_in,
                              void* d_out, int out_size)
{
    (void)in_sizes; (void)n_in; (void)out_size;
    const float* x    = (const float*)d_in[0];
    const float* W1q  = (const float*)d_in[1];
    const float* b1q  = (const float*)d_in[2];
    const float* W2q  = (const float*)d_in[3];
    const float* b2q  = (const float*)d_in[4];
    const float* W1k  = (const float*)d_in[5];
    const float* b1k  = (const float*)d_in[6];
    const float* W2k  = (const float*)d_in[7];
    const float* b2k  = (const float*)d_in[8];
    const float* W1v  = (const float*)d_in[9];
    const float* b1v  = (const float*)d_in[10];
    const float* W2v  = (const float*)d_in[11];
    const float* b2v  = (const float*)d_in[12];
    const float* ln_w = (const float*)d_in[13];
    const float* ln_b = (const float*)d_in[14];
    float* out = (float*)d_out;

    float *h, *qkv, *s, *o, *vt, *wt;
    cudaGetSymbolAddress((void**)&h,   g_h);
    cudaGetSymbolAddress((void**)&qkv, g_qkv);
    cudaGetSymbolAddress((void**)&s,   g_s);
    cudaGetSymbolAddress((void**)&o,   g_o);
    cudaGetSymbolAddress((void**)&vt,  g_vt);
    cudaGetSymbolAddress((void**)&wt,  g_wt);

    cudaFuncSetAttribute(mma_gemm<0, false, false>, cudaFuncAttributeMaxDynamicSharedMemorySize, SMEMB);
    cudaFuncSetAttribute(mma_gemm<1, false, false>, cudaFuncAttributeMaxDynamicSharedMemorySize, SMEMB);
    cudaFuncSetAttribute(mma_gemm<2, true,  false>, cudaFuncAttributeMaxDynamicSharedMemorySize, SMEMB);
    cudaFuncSetAttribute(mma_gemm<3, false, true >, cudaFuncAttributeMaxDynamicSharedMemorySize, SMEMB);

    const float inv_scale = 1.0f / sqrtf((float)C_DIM * (float)T_SEQ);
    const long long CC = (long long)C_DIM * C_DIM;
    const long long MC = (long long)M_TOTAL * C_DIM;
    const long long TC = (long long)T_SEQ * C_DIM;
    const long long TT = (long long)T_SEQ * T_SEQ;

    dim3 tb(32, 8);
    transpose_kernel<<<dim3(32, 32, 1), tb>>>(W1q, wt + 0 * CC, C_DIM, C_DIM, 0, 0);
    transpose_kernel<<<dim3(32, 32, 1), tb>>>(W1k, wt + 1 * CC, C_DIM, C_DIM, 0, 0);
    transpose_kernel<<<dim3(32, 32, 1), tb>>>(W1v, wt + 2 * CC, C_DIM, C_DIM, 0, 0);
    transpose_kernel<<<dim3(32, 32, 1), tb>>>(W2q, wt + 3 * CC, C_DIM, C_DIM, 0, 0);
    transpose_kernel<<<dim3(32, 32, 1), tb>>>(W2k, wt + 4 * CC, C_DIM, C_DIM, 0, 0);
    transpose_kernel<<<dim3(32, 32, 1), tb>>>(W2v, wt + 5 * CC, C_DIM, C_DIM, 0, 0);

    // MLP layer 1 (q,k,v fused over z): h_z = GELU(x @ W1_z + b1_z)
    mma_gemm<0, false, false><<<dim3(C_DIM / BN, M_TOTAL / BM, 3), 256, SMEMB>>>(
        x, wt, b1q, b1k, b1v, h, C_DIM, C_DIM, C_DIM, C_DIM, 0, CC, MC, 0.0f);
    // MLP layer 2: qkv_z = h_z @ W2_z + b2_z
    mma_gemm<1, false, false><<<dim3(C_DIM / BN, M_TOTAL / BM, 3), 256, SMEMB>>>(
        h, wt + 3 * CC, b2q, b2k, b2v, qkv, C_DIM, C_DIM, C_DIM, C_DIM, MC, CC, MC, 0.0f);

    // V^T per batch: [T,C] -> [C,T]
    transpose_kernel<<<dim3(C_DIM / 32, T_SEQ / 32, BATCH), tb>>>(
        qkv + 2 * MC, vt, T_SEQ, C_DIM, TC, (long long)C_DIM * T_SEQ);

    // scores: S[b,i,j] = mask(i>=j) * (q_i . k_j) * inv_scale  (upper blocks skipped)
    mma_gemm<2, true, false><<<dim3(T_SEQ / BN, T_SEQ / BM, BATCH), 256, SMEMB>>>(
        qkv, qkv + MC, nullptr, nullptr, nullptr, s,
        C_DIM, C_DIM, T_SEQ, C_DIM, TC, TC, TT, inv_scale);

    // out: O[b,i,n] = sum_{j<=i} S[b,i,j] * V[b,j,n]  (K-limit = bm+128)
    mma_gemm<3, false, true><<<dim3(C_DIM / BN, T_SEQ / BM, BATCH), 256, SMEMB>>>(
        s, vt, nullptr, nullptr, nullptr, o,
        T_SEQ, T_SEQ, C_DIM, T_SEQ, TT, (long long)C_DIM * T_SEQ, TC, 0.0f);

    layernorm_kernel<<<M_TOTAL, 256>>>(o, ln_w, ln_b, out);
}

// round 5
// speedup vs baseline: 2.2939x; 1.3165x over previous
#include <cuda_runtime.h>
#include <cuda_bf16.h>
#include <math.h>
#include <stdint.h>

// ---------------- problem constants ----------------
#define C_DIM   1024
#define T_SEQ   2048
#define BATCH   8
#define M_TOTAL (BATCH * T_SEQ)       // 16384

// ---------------- tile config ----------------
#define BM 128
#define BN 128
#define BKF 32                         // k-values per chunk
#define ROWB 80                        // smem bytes per row: 32 bf16 (64B) + 16B pad
#define TILEB (128 * ROWB)             // 10240 B per plane tile
#define STAGEB (4 * TILEB)             // Ah,Al,Bh,Bl = 40960 B per stage
#define SMEMB  (2 * STAGEB)            // 81920 B

// ---------------- scratch: split bf16 planes ----------------
__device__ __nv_bfloat16 g_xh [(size_t)M_TOTAL * C_DIM];
__device__ __nv_bfloat16 g_xl [(size_t)M_TOTAL * C_DIM];
__device__ __nv_bfloat16 g_hh [(size_t)3 * M_TOTAL * C_DIM];
__device__ __nv_bfloat16 g_hl [(size_t)3 * M_TOTAL * C_DIM];
__device__ __nv_bfloat16 g_qh [(size_t)3 * M_TOTAL * C_DIM];   // q|k|v planes
__device__ __nv_bfloat16 g_ql [(size_t)3 * M_TOTAL * C_DIM];
__device__ __nv_bfloat16 g_sh [(size_t)BATCH * T_SEQ * T_SEQ];
__device__ __nv_bfloat16 g_sl [(size_t)BATCH * T_SEQ * T_SEQ];
__device__ __nv_bfloat16 g_vth[(size_t)BATCH * C_DIM * T_SEQ];
__device__ __nv_bfloat16 g_vtl[(size_t)BATCH * C_DIM * T_SEQ];
__device__ __nv_bfloat16 g_wh [(size_t)6 * C_DIM * C_DIM];
__device__ __nv_bfloat16 g_wl [(size_t)6 * C_DIM * C_DIM];
__device__ float         g_o  [(size_t)M_TOTAL * C_DIM];

// ---------------- helpers ----------------
__device__ __forceinline__ uint32_t smem_u32(const void* p) {
    uint32_t a;
    asm("{ .reg .u64 t; cvta.to.shared.u64 t, %1; cvt.u32.u64 %0, t; }" : "=r"(a) : "l"(p));
    return a;
}
__device__ __forceinline__ void ldsm4(uint32_t* r, uint32_t addr) {
    asm volatile("ldmatrix.sync.aligned.m8n8.x4.shared.b16 {%0,%1,%2,%3}, [%4];"
                 : "=r"(r[0]), "=r"(r[1]), "=r"(r[2]), "=r"(r[3]) : "r"(addr));
}
__device__ __forceinline__ void mma16816(float* c, const uint32_t* a, uint32_t b0, uint32_t b1) {
    asm volatile("mma.sync.aligned.m16n8k16.row.col.f32.bf16.bf16.f32 "
                 "{%0,%1,%2,%3}, {%4,%5,%6,%7}, {%8,%9}, {%0,%1,%2,%3};"
                 : "+f"(c[0]), "+f"(c[1]), "+f"(c[2]), "+f"(c[3])
                 : "r"(a[0]), "r"(a[1]), "r"(a[2]), "r"(a[3]), "r"(b0), "r"(b1));
}
__device__ __forceinline__ void cpa16(uint32_t dst, const void* src) {
    asm volatile("cp.async.cg.shared.global [%0], [%1], 16;" :: "r"(dst), "l"(src));
}
__device__ __forceinline__ void cpa_commit() { asm volatile("cp.async.commit_group;" ::: "memory"); }
template <int N> __device__ __forceinline__ void cpa_wait() {
    asm volatile("cp.async.wait_group %0;" :: "n"(N) : "memory");
}
__device__ __forceinline__ float gelu_exact(float x) {
    return 0.5f * x * (1.0f + erff(x * 0.70710678118654752440f));
}
// (a,b) fp32 -> packed bf16x2 hi + lo
__device__ __forceinline__ void split2(float a, float b, uint32_t& hi, uint32_t& lo) {
    __nv_bfloat162 h = __floats2bfloat162_rn(a, b);
    __nv_bfloat162 l = __floats2bfloat162_rn(a - __bfloat162float(h.x),
                                             b - __bfloat162float(h.y));
    hi = *reinterpret_cast<uint32_t*>(&h);
    lo = *reinterpret_cast<uint32_t*>(&l);
}

// =====================================================================
// bf16x3 tensor-core GEMM on pre-split planes:
//   C[m,n] = epi( sum_k A[m,k]*B[n,k] ),  A=Ah+Al, B=Bh+Bl (bf16 planes)
//   EPI: 0 bias+GELU, 1 bias, 2 causal mask*scale, 3 plain
//   SKIP: skip CTA if bn > bm+127 (scores upper triangle)
//   CK:   K limit = bm+128 (att causal)
//   OSPLIT: write split bf16 hi/lo planes instead of fp32
// =====================================================================
template <int EPI, bool SKIP, bool CK, bool OSPLIT>
__global__ __launch_bounds__(256, 2)
void mma_gemm(const __nv_bfloat16* __restrict__ Ah, const __nv_bfloat16* __restrict__ Al,
              const __nv_bfloat16* __restrict__ Bh, const __nv_bfloat16* __restrict__ Bl,
              const float* __restrict__ b0, const float* __restrict__ b1,
              const float* __restrict__ b2,
              float* __restrict__ Co, __nv_bfloat16* __restrict__ Ch,
              __nv_bfloat16* __restrict__ Cl,
              int lda, int ldb, int ldc, int kdim,
              long long sA, long long sB, long long sC, float scale)
{
    const int bm = blockIdx.y * BM;
    const int bn = blockIdx.x * BN;
    if (SKIP && bn > bm + (BM - 1)) return;
    const int z = blockIdx.z;
    Ah += (size_t)z * sA; Al += (size_t)z * sA;
    Bh += (size_t)z * sB; Bl += (size_t)z * sB;
    if (OSPLIT) { Ch += (size_t)z * sC; Cl += (size_t)z * sC; }
    else        { Co += (size_t)z * sC; }
    const float* bias = (z == 0) ? b0 : ((z == 1) ? b1 : b2);

    extern __shared__ __align__(128) char smem[];
    const uint32_t sb = smem_u32(smem);
    const int tid = threadIdx.x, lane = tid & 31, wid = tid >> 5;
    const int wm = (wid >> 1) * 32;
    const int wn = (wid & 1) * 64;

    const int kend = CK ? (bm + BM) : kdim;
    const int NC = kend / BKF;

    // cp.async mapping: per thread 2 rows x 1 seg per plane
    const int r0 = tid >> 2;
    const int kc = (tid & 3) * 8;          // bf16 element offset (8 per 16B)

    auto issue = [&](int c) {
        const int k0 = c * BKF;
        const uint32_t stg = sb + (uint32_t)(c & 1) * STAGEB;
        #pragma unroll
        for (int h = 0; h < 2; h++) {
            const int r = r0 + h * 64;
            const uint32_t soff = (uint32_t)r * ROWB + (uint32_t)kc * 2;
            cpa16(stg + 0 * TILEB + soff, Ah + (size_t)(bm + r) * lda + k0 + kc);
            cpa16(stg + 1 * TILEB + soff, Al + (size_t)(bm + r) * lda + k0 + kc);
            cpa16(stg + 2 * TILEB + soff, Bh + (size_t)(bn + r) * ldb + k0 + kc);
            cpa16(stg + 3 * TILEB + soff, Bl + (size_t)(bn + r) * ldb + k0 + kc);
        }
        cpa_commit();
    };

    float acc[2][8][4];
    #pragma unroll
    for (int mt = 0; mt < 2; mt++)
        #pragma unroll
        for (int nt = 0; nt < 8; nt++)
            #pragma unroll
            for (int e = 0; e < 4; e++) acc[mt][nt][e] = 0.0f;

    const uint32_t lrow = lane & 15;
    const uint32_t lcol = (uint32_t)(lane >> 4) * 16;

    issue(0);
    issue(1);

    for (int c = 0; c < NC; c++) {
        if (c < NC - 1) cpa_wait<1>(); else cpa_wait<0>();
        __syncthreads();
        const uint32_t stg = sb + (uint32_t)(c & 1) * STAGEB;

        #pragma unroll
        for (int s = 0; s < 2; s++) {
            uint32_t ah[2][4], al[2][4];
            #pragma unroll
            for (int mt = 0; mt < 2; mt++) {
                const uint32_t ad = stg + (uint32_t)(wm + mt * 16 + lrow) * ROWB + s * 32 + lcol;
                ldsm4(ah[mt], ad);
                ldsm4(al[mt], ad + 1 * TILEB);
            }
            #pragma unroll
            for (int ng = 0; ng < 4; ng++) {
                uint32_t bh[4], bl[4];
                const uint32_t bd = stg + (uint32_t)(wn + ng * 16 + lrow) * ROWB + s * 32 + lcol;
                ldsm4(bh, bd + 2 * TILEB);
                ldsm4(bl, bd + 3 * TILEB);
                #pragma unroll
                for (int mt = 0; mt < 2; mt++) {
                    mma16816(acc[mt][2 * ng],     ah[mt], bh[0], bh[2]);
                    mma16816(acc[mt][2 * ng],     ah[mt], bl[0], bl[2]);
                    mma16816(acc[mt][2 * ng],     al[mt], bh[0], bh[2]);
                    mma16816(acc[mt][2 * ng + 1], ah[mt], bh[1], bh[3]);
                    mma16816(acc[mt][2 * ng + 1], ah[mt], bl[1], bl[3]);
                    mma16816(acc[mt][2 * ng + 1], al[mt], bh[1], bh[3]);
                }
            }
        }
        __syncthreads();
        if (c + 2 < NC) issue(c + 2);
    }

    // ---- epilogue ----
    const int erow = lane >> 2;
    const int ecol = (lane & 3) * 2;
    #pragma unroll
    for (int mt = 0; mt < 2; mt++) {
        #pragma unroll
        for (int nt = 0; nt < 8; nt++) {
            const int gr = bm + wm + mt * 16 + erow;
            const int gc = bn + wn + nt * 8 + ecol;
            float v0 = acc[mt][nt][0], v1 = acc[mt][nt][1];
            float v2 = acc[mt][nt][2], v3 = acc[mt][nt][3];
            if (EPI == 0) {
                const float bb0 = bias[gc], bb1 = bias[gc + 1];
                v0 = gelu_exact(v0 + bb0); v1 = gelu_exact(v1 + bb1);
                v2 = gelu_exact(v2 + bb0); v3 = gelu_exact(v3 + bb1);
            } else if (EPI == 1) {
                const float bb0 = bias[gc], bb1 = bias[gc + 1];
                v0 += bb0; v1 += bb1; v2 += bb0; v3 += bb1;
            } else if (EPI == 2) {
                v0 = (gr     >= gc    ) ? v0 * scale : 0.0f;
                v1 = (gr     >= gc + 1) ? v1 * scale : 0.0f;
                v2 = (gr + 8 >= gc    ) ? v2 * scale : 0.0f;
                v3 = (gr + 8 >= gc + 1) ? v3 * scale : 0.0f;
            }
            if (OSPLIT) {
                uint32_t h01, l01, h23, l23;
                split2(v0, v1, h01, l01);
                split2(v2, v3, h23, l23);
                *reinterpret_cast<uint32_t*>(Ch + (size_t)gr * ldc + gc)       = h01;
                *reinterpret_cast<uint32_t*>(Cl + (size_t)gr * ldc + gc)       = l01;
                *reinterpret_cast<uint32_t*>(Ch + (size_t)(gr + 8) * ldc + gc) = h23;
                *reinterpret_cast<uint32_t*>(Cl + (size_t)(gr + 8) * ldc + gc) = l23;
            } else {
                *reinterpret_cast<float2*>(Co + (size_t)gr * ldc + gc)       = make_float2(v0, v1);
                *reinterpret_cast<float2*>(Co + (size_t)(gr + 8) * ldc + gc) = make_float2(v2, v3);
            }
        }
    }
}

// =====================================================================
// x split: fp32 -> bf16 hi/lo planes (elementwise, float4 vectorized)
// =====================================================================
__global__ __launch_bounds__(256) void split_x_kernel(
    const float4* __restrict__ x, uint2* __restrict__ hi, uint2* __restrict__ lo)
{
    const int i = blockIdx.x * 256 + threadIdx.x;
    float4 v = x[i];
    uint32_t h01, l01, h23, l23;
    split2(v.x, v.y, h01, l01);
    split2(v.z, v.w, h23, l23);
    hi[i] = make_uint2(h01, h23);
    lo[i] = make_uint2(l01, l23);
}

// =====================================================================
// weight transpose+split: W[k,n] fp32 -> wh/wl [n,k] bf16
// =====================================================================
__global__ __launch_bounds__(256) void wsplit_kernel(
    const float* __restrict__ W, __nv_bfloat16* __restrict__ wh, __nv_bfloat16* __restrict__ wl)
{
    __shared__ float t[32][33];
    const int n0 = blockIdx.x * 32, k0 = blockIdx.y * 32;
    const int tx = threadIdx.x, ty = threadIdx.y;
    #pragma unroll
    for (int i = ty; i < 32; i += 8)
        t[i][tx] = W[(size_t)(k0 + i) * C_DIM + n0 + tx];
    __syncthreads();
    #pragma unroll
    for (int i = ty; i < 32; i += 8) {
        float v = t[tx][i];
        __nv_bfloat16 h = __float2bfloat16(v);
        wh[(size_t)(n0 + i) * C_DIM + k0 + tx] = h;
        wl[(size_t)(n0 + i) * C_DIM + k0 + tx] = __float2bfloat16(v - __bfloat162float(h));
    }
}

// =====================================================================
// V transpose (both planes): [T,C] -> [C,T], batched over z
// =====================================================================
__global__ __launch_bounds__(256) void vtrans_kernel(
    const __nv_bfloat16* __restrict__ vh, const __nv_bfloat16* __restrict__ vl,
    __nv_bfloat16* __restrict__ vth, __nv_bfloat16* __restrict__ vtl)
{
    __shared__ ushort th[32][33], tl[32][33];
    const int z = blockIdx.z;
    const ushort* ph = reinterpret_cast<const ushort*>(vh) + (size_t)z * T_SEQ * C_DIM;
    const ushort* pl = reinterpret_cast<const ushort*>(vl) + (size_t)z * T_SEQ * C_DIM;
    ushort* oh = reinterpret_cast<ushort*>(vth) + (size_t)z * C_DIM * T_SEQ;
    ushort* ol = reinterpret_cast<ushort*>(vtl) + (size_t)z * C_DIM * T_SEQ;
    const int c0 = blockIdx.x * 32, r0 = blockIdx.y * 32;
    const int tx = threadIdx.x, ty = threadIdx.y;
    #pragma unroll
    for (int i = ty; i < 32; i += 8) {
        th[i][tx] = ph[(size_t)(r0 + i) * C_DIM + c0 + tx];
        tl[i][tx] = pl[(size_t)(r0 + i) * C_DIM + c0 + tx];
    }
    __syncthreads();
    #pragma unroll
    for (int i = ty; i < 32; i += 8) {
        oh[(size_t)(c0 + i) * T_SEQ + r0 + tx] = th[tx][i];
        ol[(size_t)(c0 + i) * T_SEQ + r0 + tx] = tl[tx][i];
    }
}

// =====================================================================
// LayerNorm over last dim (C=1024), weight+bias, eps=1e-5
// =====================================================================
__global__ __launch_bounds__(256) void layernorm_kernel(
    const float* __restrict__ X, const float* __restrict__ w,
    const float* __restrict__ bia, float* __restrict__ out)
{
    const int row = blockIdx.x;
    const int tid = threadIdx.x;
    const float* xr = X + (size_t)row * C_DIM;

    float4 v = *reinterpret_cast<const float4*>(&xr[tid * 4]);
    float s  = v.x + v.y + v.z + v.w;
    float sq = v.x * v.x + v.y * v.y + v.z * v.z + v.w * v.w;
    #pragma unroll
    for (int off = 16; off > 0; off >>= 1) {
        s  += __shfl_xor_sync(0xffffffffu, s,  off);
        sq += __shfl_xor_sync(0xffffffffu, sq, off);
    }
    __shared__ float red_s[8], red_q[8];
    const int wid = tid >> 5;
    if ((tid & 31) == 0) { red_s[wid] = s; red_q[wid] = sq; }
    __syncthreads();
    __shared__ float mu_s, inv_s;
    if (tid == 0) {
        float ts = 0.f, tq = 0.f;
        #pragma unroll
        for (int i = 0; i < 8; i++) { ts += red_s[i]; tq += red_q[i]; }
        float mu  = ts * (1.0f / C_DIM);
        float var = tq * (1.0f / C_DIM) - mu * mu;
        mu_s = mu; inv_s = rsqrtf(var + 1e-5f);
    }
    __syncthreads();
    const float mu = mu_s, inv = inv_s;
    float4 wv = *reinterpret_cast<const float4*>(&w[tid * 4]);
    float4 bv = *reinterpret_cast<const float4*>(&bia[tid * 4]);
    float4 o;
    o.x = (v.x - mu) * inv * wv.x + bv.x;
    o.y = (v.y - mu) * inv * wv.y + bv.y;
    o.z = (v.z - mu) * inv * wv.z + bv.z;
    o.w = (v.w - mu) * inv * wv.w + bv.w;
    *reinterpret_cast<float4*>(&out[(size_t)row * C_DIM + tid * 4]) = o;
}

// =====================================================================
// launch
// =====================================================================
extern "C" void kernel_launch(void* const* d_in, const int* in_sizes, int n_in,
                              void* d_out, int out_size)
{
    (void)in_sizes; (void)n_in; (void)out_size;
    const float* x    = (const float*)d_in[0];
    const float* W1q  = (const float*)d_in[1];
    const float* b1q  = (const float*)d_in[2];
    const float* W2q  = (const float*)d_in[3];
    const float* b2q  = (const float*)d_in[4];
    const float* W1k  = (const float*)d_in[5];
    const float* b1k  = (const float*)d_in[6];
    const float* W2k  = (const float*)d_in[7];
    const float* b2k  = (const float*)d_in[8];
    const float* W1v  = (const float*)d_in[9];
    const float* b1v  = (const float*)d_in[10];
    const float* W2v  = (const float*)d_in[11];
    const float* b2v  = (const float*)d_in[12];
    const float* ln_w = (const float*)d_in[13];
    const float* ln_b = (const float*)d_in[14];
    float* out = (float*)d_out;

    __nv_bfloat16 *xh, *xl, *hh, *hl, *qh, *ql, *sh, *sl, *vth, *vtl, *wh, *wl;
    float* o;
    cudaGetSymbolAddress((void**)&xh,  g_xh);  cudaGetSymbolAddress((void**)&xl,  g_xl);
    cudaGetSymbolAddress((void**)&hh,  g_hh);  cudaGetSymbolAddress((void**)&hl,  g_hl);
    cudaGetSymbolAddress((void**)&qh,  g_qh);  cudaGetSymbolAddress((void**)&ql,  g_ql);
    cudaGetSymbolAddress((void**)&sh,  g_sh);  cudaGetSymbolAddress((void**)&sl,  g_sl);
    cudaGetSymbolAddress((void**)&vth, g_vth); cudaGetSymbolAddress((void**)&vtl, g_vtl);
    cudaGetSymbolAddress((void**)&wh,  g_wh);  cudaGetSymbolAddress((void**)&wl,  g_wl);
    cudaGetSymbolAddress((void**)&o,   g_o);

    cudaFuncSetAttribute(mma_gemm<0, false, false, true >, cudaFuncAttributeMaxDynamicSharedMemorySize, SMEMB);
    cudaFuncSetAttribute(mma_gemm<1, false, false, true >, cudaFuncAttributeMaxDynamicSharedMemorySize, SMEMB);
    cudaFuncSetAttribute(mma_gemm<2, true,  false, true >, cudaFuncAttributeMaxDynamicSharedMemorySize, SMEMB);
    cudaFuncSetAttribute(mma_gemm<3, false, true,  false>, cudaFuncAttributeMaxDynamicSharedMemorySize, SMEMB);

    const float inv_scale = 1.0f / sqrtf((float)C_DIM * (float)T_SEQ);
    const long long CC = (long long)C_DIM * C_DIM;
    const long long MC = (long long)M_TOTAL * C_DIM;
    const long long TC = (long long)T_SEQ * C_DIM;
    const long long TT = (long long)T_SEQ * T_SEQ;

    // ---- prep: split x, transpose+split weights ----
    split_x_kernel<<<M_TOTAL * C_DIM / (256 * 4), 256>>>(
        (const float4*)x, (uint2*)xh, (uint2*)xl);
    dim3 tb(32, 8);
    wsplit_kernel<<<dim3(32, 32), tb>>>(W1q, wh + 0 * CC, wl + 0 * CC);
    wsplit_kernel<<<dim3(32, 32), tb>>>(W1k, wh + 1 * CC, wl + 1 * CC);
    wsplit_kernel<<<dim3(32, 32), tb>>>(W1v, wh + 2 * CC, wl + 2 * CC);
    wsplit_kernel<<<dim3(32, 32), tb>>>(W2q, wh + 3 * CC, wl + 3 * CC);
    wsplit_kernel<<<dim3(32, 32), tb>>>(W2k, wh + 4 * CC, wl + 4 * CC);
    wsplit_kernel<<<dim3(32, 32), tb>>>(W2v, wh + 5 * CC, wl + 5 * CC);

    // ---- MLP layer 1: h_z = GELU(x @ W1_z + b1_z), split output ----
    mma_gemm<0, false, false, true><<<dim3(C_DIM / BN, M_TOTAL / BM, 3), 256, SMEMB>>>(
        xh, xl, wh, wl, b1q, b1k, b1v, nullptr, hh, hl,
        C_DIM, C_DIM, C_DIM, C_DIM, 0, CC, MC, 0.0f);
    // ---- MLP layer 2: qkv_z = h_z @ W2_z + b2_z, split output ----
    mma_gemm<1, false, false, true><<<dim3(C_DIM / BN, M_TOTAL / BM, 3), 256, SMEMB>>>(
        hh, hl, wh + 3 * CC, wl + 3 * CC, b2q, b2k, b2v, nullptr, qh, ql,
        C_DIM, C_DIM, C_DIM, C_DIM, MC, CC, MC, 0.0f);

    // ---- V^T per batch (both planes) ----
    vtrans_kernel<<<dim3(C_DIM / 32, T_SEQ / 32, BATCH), tb>>>(
        qh + 2 * MC, ql + 2 * MC, vth, vtl);

    // ---- scores: S = mask(i>=j) * (q.k) * inv_scale, split output ----
    mma_gemm<2, true, false, true><<<dim3(T_SEQ / BN, T_SEQ / BM, BATCH), 256, SMEMB>>>(
        qh, ql, qh + MC, ql + MC, nullptr, nullptr, nullptr, nullptr, sh, sl,
        C_DIM, C_DIM, T_SEQ, C_DIM, TC, TC, TT, inv_scale);

    // ---- att: O = S @ V (causal K-limit), fp32 output ----
    mma_gemm<3, false, true, false><<<dim3(C_DIM / BN, T_SEQ / BM, BATCH), 256, SMEMB>>>(
        sh, sl, vth, vtl, nullptr, nullptr, nullptr, o, nullptr, nullptr,
        T_SEQ, T_SEQ, C_DIM, T_SEQ, TT, (long long)C_DIM * T_SEQ, TC, 0.0f);

    layernorm_kernel<<<M_TOTAL, 256>>>(o, ln_w, ln_b, out);
}

// round 6
// speedup vs baseline: 2.5757x; 1.1228x over previous
#include <cuda_runtime.h>
#include <cuda_bf16.h>
#include <math.h>
#include <stdint.h>

// ---------------- problem constants ----------------
#define C_DIM   1024
#define T_SEQ   2048
#define BATCH   8
#define M_TOTAL (BATCH * T_SEQ)       // 16384

// ---------------- tile config ----------------
#define BM 128
#define BN 128
#define BKF 32                         // k-values per chunk
#define ROWB 64                        // 32 bf16 per row, XOR-swizzled chunks
#define TILEB (128 * ROWB)             // 8192 B per plane tile
#define STAGEB (4 * TILEB)             // Ah,Al,Bh,Bl = 32768 B per stage
#define NSTAGE 3
#define SMEMB  (NSTAGE * STAGEB)       // 98304 B

// ---------------- scratch: split bf16 planes ----------------
__device__ __nv_bfloat16 g_xh [(size_t)M_TOTAL * C_DIM];
__device__ __nv_bfloat16 g_xl [(size_t)M_TOTAL * C_DIM];
__device__ __nv_bfloat16 g_hh [(size_t)3 * M_TOTAL * C_DIM];
__device__ __nv_bfloat16 g_hl [(size_t)3 * M_TOTAL * C_DIM];
__device__ __nv_bfloat16 g_qh [(size_t)3 * M_TOTAL * C_DIM];   // q|k|v planes
__device__ __nv_bfloat16 g_ql [(size_t)3 * M_TOTAL * C_DIM];
__device__ __nv_bfloat16 g_sh [(size_t)BATCH * T_SEQ * T_SEQ];
__device__ __nv_bfloat16 g_sl [(size_t)BATCH * T_SEQ * T_SEQ];
__device__ __nv_bfloat16 g_vth[(size_t)BATCH * C_DIM * T_SEQ];
__device__ __nv_bfloat16 g_vtl[(size_t)BATCH * C_DIM * T_SEQ];
__device__ __nv_bfloat16 g_wh [(size_t)6 * C_DIM * C_DIM];
__device__ __nv_bfloat16 g_wl [(size_t)6 * C_DIM * C_DIM];
__device__ float         g_o  [(size_t)M_TOTAL * C_DIM];

// ---------------- helpers ----------------
__device__ __forceinline__ uint32_t smem_u32(const void* p) {
    uint32_t a;
    asm("{ .reg .u64 t; cvta.to.shared.u64 t, %1; cvt.u32.u64 %0, t; }" : "=r"(a) : "l"(p));
    return a;
}
__device__ __forceinline__ void ldsm4(uint32_t* r, uint32_t addr) {
    asm volatile("ldmatrix.sync.aligned.m8n8.x4.shared.b16 {%0,%1,%2,%3}, [%4];"
                 : "=r"(r[0]), "=r"(r[1]), "=r"(r[2]), "=r"(r[3]) : "r"(addr));
}
__device__ __forceinline__ void mma16816(float* c, const uint32_t* a, uint32_t b0, uint32_t b1) {
    asm volatile("mma.sync.aligned.m16n8k16.row.col.f32.bf16.bf16.f32 "
                 "{%0,%1,%2,%3}, {%4,%5,%6,%7}, {%8,%9}, {%0,%1,%2,%3};"
                 : "+f"(c[0]), "+f"(c[1]), "+f"(c[2]), "+f"(c[3])
                 : "r"(a[0]), "r"(a[1]), "r"(a[2]), "r"(a[3]), "r"(b0), "r"(b1));
}
__device__ __forceinline__ void cpa16(uint32_t dst, const void* src) {
    asm volatile("cp.async.cg.shared.global [%0], [%1], 16;" :: "r"(dst), "l"(src));
}
__device__ __forceinline__ void cpa_commit() { asm volatile("cp.async.commit_group;" ::: "memory"); }
template <int N> __device__ __forceinline__ void cpa_wait() {
    asm volatile("cp.async.wait_group %0;" :: "n"(N) : "memory");
}
__device__ __forceinline__ float gelu_exact(float x) {
    return 0.5f * x * (1.0f + erff(x * 0.70710678118654752440f));
}
// (a,b) fp32 -> packed bf16x2 hi + lo
__device__ __forceinline__ void split2(float a, float b, uint32_t& hi, uint32_t& lo) {
    __nv_bfloat162 h = __floats2bfloat162_rn(a, b);
    __nv_bfloat162 l = __floats2bfloat162_rn(a - __bfloat162float(h.x),
                                             b - __bfloat162float(h.y));
    hi = *reinterpret_cast<uint32_t*>(&h);
    lo = *reinterpret_cast<uint32_t*>(&l);
}

// =====================================================================
// bf16x3 tensor-core GEMM on pre-split planes, 3-stage cp.async ring.
//   C[m,n] = epi( sum_k A[m,k]*B[n,k] ),  A=Ah+Al, B=Bh+Bl
//   EPI: 0 bias+GELU, 1 bias, 2 causal mask*scale, 3 plain
//   SKIP: skip CTA if bn > bm+127; CK: K limit = bm+128
//   OSPLIT: write split bf16 hi/lo planes instead of fp32
// =====================================================================
template <int EPI, bool SKIP, bool CK, bool OSPLIT>
__global__ __launch_bounds__(256, 2)
void mma_gemm(const __nv_bfloat16* __restrict__ Ah, const __nv_bfloat16* __restrict__ Al,
              const __nv_bfloat16* __restrict__ Bh, const __nv_bfloat16* __restrict__ Bl,
              const float* __restrict__ b0, const float* __restrict__ b1,
              const float* __restrict__ b2,
              float* __restrict__ Co, __nv_bfloat16* __restrict__ Ch,
              __nv_bfloat16* __restrict__ Cl,
              int lda, int ldb, int ldc, int kdim,
              long long sA, long long sB, long long sC, float scale)
{
    const int bm = blockIdx.y * BM;
    const int bn = blockIdx.x * BN;
    if (SKIP && bn > bm + (BM - 1)) return;
    const int z = blockIdx.z;
    Ah += (size_t)z * sA; Al += (size_t)z * sA;
    Bh += (size_t)z * sB; Bl += (size_t)z * sB;
    if (OSPLIT) { Ch += (size_t)z * sC; Cl += (size_t)z * sC; }
    else        { Co += (size_t)z * sC; }
    const float* bias = (z == 0) ? b0 : ((z == 1) ? b1 : b2);

    extern __shared__ __align__(128) char smem[];
    const uint32_t sb = smem_u32(smem);
    const int tid = threadIdx.x, lane = tid & 31, wid = tid >> 5;
    const int wm = (wid >> 1) * 32;
    const int wn = (wid & 1) * 64;

    const int kend = CK ? (bm + BM) : kdim;
    const int NC = kend / BKF;

    // cp.async mapping: r0 = row, chunk c = tid&3, XOR-swizzled by (row>>1)&3
    const int r0 = tid >> 2;
    const int ck = tid & 3;
    const uint32_t sw0 = (uint32_t)((r0 >> 1) & 3);             // same for r0 and r0+64
    const uint32_t so0 = (uint32_t)r0 * ROWB + ((ck ^ sw0) * 16);
    const uint32_t so1 = so0 + 64u * ROWB;
    const int kc = ck * 8;                                       // bf16 elem offset

    auto issue = [&](int c) {
        const int k0 = c * BKF;
        const uint32_t stg = sb + (uint32_t)(c % NSTAGE) * STAGEB;
        cpa16(stg + 0 * TILEB + so0, Ah + (size_t)(bm + r0) * lda + k0 + kc);
        cpa16(stg + 1 * TILEB + so0, Al + (size_t)(bm + r0) * lda + k0 + kc);
        cpa16(stg + 2 * TILEB + so0, Bh + (size_t)(bn + r0) * ldb + k0 + kc);
        cpa16(stg + 3 * TILEB + so0, Bl + (size_t)(bn + r0) * ldb + k0 + kc);
        cpa16(stg + 0 * TILEB + so1, Ah + (size_t)(bm + r0 + 64) * lda + k0 + kc);
        cpa16(stg + 1 * TILEB + so1, Al + (size_t)(bm + r0 + 64) * lda + k0 + kc);
        cpa16(stg + 2 * TILEB + so1, Bh + (size_t)(bn + r0 + 64) * ldb + k0 + kc);
        cpa16(stg + 3 * TILEB + so1, Bl + (size_t)(bn + r0 + 64) * ldb + k0 + kc);
        cpa_commit();
    };

    float acc[2][8][4];
    #pragma unroll
    for (int mt = 0; mt < 2; mt++)
        #pragma unroll
        for (int nt = 0; nt < 8; nt++)
            #pragma unroll
            for (int e = 0; e < 4; e++) acc[mt][nt][e] = 0.0f;

    const uint32_t lrow = lane & 15;
    const uint32_t lc16 = (uint32_t)(lane >> 4);   // chunk sub-index from lane

    // precompute per-thread ldmatrix row offsets (swizzle depends on row)
    uint32_t aoff[2], boff[4];
    #pragma unroll
    for (int mt = 0; mt < 2; mt++) {
        const uint32_t row = (uint32_t)(wm + mt * 16) + lrow;
        aoff[mt] = row * ROWB + (((row >> 1) & 3) << 4);   // XOR applied to chunk later
    }
    #pragma unroll
    for (int ng = 0; ng < 4; ng++) {
        const uint32_t row = (uint32_t)(wn + ng * 16) + lrow;
        boff[ng] = row * ROWB + (((row >> 1) & 3) << 4);
    }
    // note: chunk XOR is (chunk ^ sw); we fold sw into base via XOR identity:
    //   addr = row*64 + ((chunk ^ sw)<<4) = row*64 + (chunk<<4 ^ sw<<4)

    issue(0);
    if (NC > 1) issue(1);

    for (int c = 0; c < NC; c++) {
        if (c + 1 < NC) cpa_wait<1>(); else cpa_wait<0>();
        __syncthreads();
        if (c + 2 < NC) issue(c + 2);    // safe: targets buffer consumed at c-1
        const uint32_t stg = sb + (uint32_t)(c % NSTAGE) * STAGEB;

        #pragma unroll
        for (int s = 0; s < 2; s++) {
            const uint32_t chunk = ((uint32_t)s * 2 + lc16) << 4;   // byte sel before XOR
            uint32_t ah[2][4], al[2][4];
            #pragma unroll
            for (int mt = 0; mt < 2; mt++) {
                const uint32_t ad = stg + (aoff[mt] ^ chunk);
                ldsm4(ah[mt], ad);
                ldsm4(al[mt], ad + 1 * TILEB);
            }
            #pragma unroll
            for (int ng = 0; ng < 4; ng++) {
                uint32_t bh[4], bl[4];
                const uint32_t bd = stg + (boff[ng] ^ chunk);
                ldsm4(bh, bd + 2 * TILEB);
                ldsm4(bl, bd + 3 * TILEB);
                #pragma unroll
                for (int mt = 0; mt < 2; mt++) {
                    mma16816(acc[mt][2 * ng],     ah[mt], bh[0], bh[2]);
                    mma16816(acc[mt][2 * ng],     ah[mt], bl[0], bl[2]);
                    mma16816(acc[mt][2 * ng],     al[mt], bh[0], bh[2]);
                    mma16816(acc[mt][2 * ng + 1], ah[mt], bh[1], bh[3]);
                    mma16816(acc[mt][2 * ng + 1], ah[mt], bl[1], bl[3]);
                    mma16816(acc[mt][2 * ng + 1], al[mt], bh[1], bh[3]);
                }
            }
        }
    }

    // ---- epilogue ----
    const int erow = lane >> 2;
    const int ecol = (lane & 3) * 2;
    #pragma unroll
    for (int mt = 0; mt < 2; mt++) {
        #pragma unroll
        for (int nt = 0; nt < 8; nt++) {
            const int gr = bm + wm + mt * 16 + erow;
            const int gc = bn + wn + nt * 8 + ecol;
            float v0 = acc[mt][nt][0], v1 = acc[mt][nt][1];
            float v2 = acc[mt][nt][2], v3 = acc[mt][nt][3];
            if (EPI == 0) {
                const float bb0 = bias[gc], bb1 = bias[gc + 1];
                v0 = gelu_exact(v0 + bb0); v1 = gelu_exact(v1 + bb1);
                v2 = gelu_exact(v2 + bb0); v3 = gelu_exact(v3 + bb1);
            } else if (EPI == 1) {
                const float bb0 = bias[gc], bb1 = bias[gc + 1];
                v0 += bb0; v1 += bb1; v2 += bb0; v3 += bb1;
            } else if (EPI == 2) {
                v0 = (gr     >= gc    ) ? v0 * scale : 0.0f;
                v1 = (gr     >= gc + 1) ? v1 * scale : 0.0f;
                v2 = (gr + 8 >= gc    ) ? v2 * scale : 0.0f;
                v3 = (gr + 8 >= gc + 1) ? v3 * scale : 0.0f;
            }
            if (OSPLIT) {
                uint32_t h01, l01, h23, l23;
                split2(v0, v1, h01, l01);
                split2(v2, v3, h23, l23);
                *reinterpret_cast<uint32_t*>(Ch + (size_t)gr * ldc + gc)       = h01;
                *reinterpret_cast<uint32_t*>(Cl + (size_t)gr * ldc + gc)       = l01;
                *reinterpret_cast<uint32_t*>(Ch + (size_t)(gr + 8) * ldc + gc) = h23;
                *reinterpret_cast<uint32_t*>(Cl + (size_t)(gr + 8) * ldc + gc) = l23;
            } else {
                *reinterpret_cast<float2*>(Co + (size_t)gr * ldc + gc)       = make_float2(v0, v1);
                *reinterpret_cast<float2*>(Co + (size_t)(gr + 8) * ldc + gc) = make_float2(v2, v3);
            }
        }
    }
}

// =====================================================================
// x split: fp32 -> bf16 hi/lo planes
// =====================================================================
__global__ __launch_bounds__(256) void split_x_kernel(
    const float4* __restrict__ x, uint2* __restrict__ hi, uint2* __restrict__ lo)
{
    const int i = blockIdx.x * 256 + threadIdx.x;
    float4 v = x[i];
    uint32_t h01, l01, h23, l23;
    split2(v.x, v.y, h01, l01);
    split2(v.z, v.w, h23, l23);
    hi[i] = make_uint2(h01, h23);
    lo[i] = make_uint2(l01, l23);
}

// =====================================================================
// weight transpose+split: W[k,n] fp32 -> wh/wl [n,k] bf16
// =====================================================================
__global__ __launch_bounds__(256) void wsplit_kernel(
    const float* __restrict__ W, __nv_bfloat16* __restrict__ wh, __nv_bfloat16* __restrict__ wl)
{
    __shared__ float t[32][33];
    const int n0 = blockIdx.x * 32, k0 = blockIdx.y * 32;
    const int tx = threadIdx.x, ty = threadIdx.y;
    #pragma unroll
    for (int i = ty; i < 32; i += 8)
        t[i][tx] = W[(size_t)(k0 + i) * C_DIM + n0 + tx];
    __syncthreads();
    #pragma unroll
    for (int i = ty; i < 32; i += 8) {
        float v = t[tx][i];
        __nv_bfloat16 h = __float2bfloat16(v);
        wh[(size_t)(n0 + i) * C_DIM + k0 + tx] = h;
        wl[(size_t)(n0 + i) * C_DIM + k0 + tx] = __float2bfloat16(v - __bfloat162float(h));
    }
}

// =====================================================================
// V transpose (both planes): [T,C] -> [C,T], batched over z
// =====================================================================
__global__ __launch_bounds__(256) void vtrans_kernel(
    const __nv_bfloat16* __restrict__ vh, const __nv_bfloat16* __restrict__ vl,
    __nv_bfloat16* __restrict__ vth, __nv_bfloat16* __restrict__ vtl)
{
    __shared__ ushort th[32][33], tl[32][33];
    const int z = blockIdx.z;
    const ushort* ph = reinterpret_cast<const ushort*>(vh) + (size_t)z * T_SEQ * C_DIM;
    const ushort* pl = reinterpret_cast<const ushort*>(vl) + (size_t)z * T_SEQ * C_DIM;
    ushort* oh = reinterpret_cast<ushort*>(vth) + (size_t)z * C_DIM * T_SEQ;
    ushort* ol = reinterpret_cast<ushort*>(vtl) + (size_t)z * C_DIM * T_SEQ;
    const int c0 = blockIdx.x * 32, r0 = blockIdx.y * 32;
    const int tx = threadIdx.x, ty = threadIdx.y;
    #pragma unroll
    for (int i = ty; i < 32; i += 8) {
        th[i][tx] = ph[(size_t)(r0 + i) * C_DIM + c0 + tx];
        tl[i][tx] = pl[(size_t)(r0 + i) * C_DIM + c0 + tx];
    }
    __syncthreads();
    #pragma unroll
    for (int i = ty; i < 32; i += 8) {
        oh[(size_t)(c0 + i) * T_SEQ + r0 + tx] = th[tx][i];
        ol[(size_t)(c0 + i) * T_SEQ + r0 + tx] = tl[tx][i];
    }
}

// =====================================================================
// LayerNorm over last dim (C=1024), weight+bias, eps=1e-5
// =====================================================================
__global__ __launch_bounds__(256) void layernorm_kernel(
    const float* __restrict__ X, const float* __restrict__ w,
    const float* __restrict__ bia, float* __restrict__ out)
{
    const int row = blockIdx.x;
    const int tid = threadIdx.x;
    const float* xr = X + (size_t)row * C_DIM;

    float4 v = *reinterpret_cast<const float4*>(&xr[tid * 4]);
    float s  = v.x + v.y + v.z + v.w;
    float sq = v.x * v.x + v.y * v.y + v.z * v.z + v.w * v.w;
    #pragma unroll
    for (int off = 16; off > 0; off >>= 1) {
        s  += __shfl_xor_sync(0xffffffffu, s,  off);
        sq += __shfl_xor_sync(0xffffffffu, sq, off);
    }
    __shared__ float red_s[8], red_q[8];
    const int wid = tid >> 5;
    if ((tid & 31) == 0) { red_s[wid] = s; red_q[wid] = sq; }
    __syncthreads();
    __shared__ float mu_s, inv_s;
    if (tid == 0) {
        float ts = 0.f, tq = 0.f;
        #pragma unroll
        for (int i = 0; i < 8; i++) { ts += red_s[i]; tq += red_q[i]; }
        float mu  = ts * (1.0f / C_DIM);
        float var = tq * (1.0f / C_DIM) - mu * mu;
        mu_s = mu; inv_s = rsqrtf(var + 1e-5f);
    }
    __syncthreads();
    const float mu = mu_s, inv = inv_s;
    float4 wv = *reinterpret_cast<const float4*>(&w[tid * 4]);
    float4 bv = *reinterpret_cast<const float4*>(&bia[tid * 4]);
    float4 o;
    o.x = (v.x - mu) * inv * wv.x + bv.x;
    o.y = (v.y - mu) * inv * wv.y + bv.y;
    o.z = (v.z - mu) * inv * wv.z + bv.z;
    o.w = (v.w - mu) * inv * wv.w + bv.w;
    *reinterpret_cast<float4*>(&out[(size_t)row * C_DIM + tid * 4]) = o;
}

// =====================================================================
// launch
// =====================================================================
extern "C" void kernel_launch(void* const* d_in, const int* in_sizes, int n_in,
                              void* d_out, int out_size)
{
    (void)in_sizes; (void)n_in; (void)out_size;
    const float* x    = (const float*)d_in[0];
    const float* W1q  = (const float*)d_in[1];
    const float* b1q  = (const float*)d_in[2];
    const float* W2q  = (const float*)d_in[3];
    const float* b2q  = (const float*)d_in[4];
    const float* W1k  = (const float*)d_in[5];
    const float* b1k  = (const float*)d_in[6];
    const float* W2k  = (const float*)d_in[7];
    const float* b2k  = (const float*)d_in[8];
    const float* W1v  = (const float*)d_in[9];
    const float* b1v  = (const float*)d_in[10];
    const float* W2v  = (const float*)d_in[11];
    const float* b2v  = (const float*)d_in[12];
    const float* ln_w = (const float*)d_in[13];
    const float* ln_b = (const float*)d_in[14];
    float* out = (float*)d_out;

    __nv_bfloat16 *xh, *xl, *hh, *hl, *qh, *ql, *sh, *sl, *vth, *vtl, *wh, *wl;
    float* o;
    cudaGetSymbolAddress((void**)&xh,  g_xh);  cudaGetSymbolAddress((void**)&xl,  g_xl);
    cudaGetSymbolAddress((void**)&hh,  g_hh);  cudaGetSymbolAddress((void**)&hl,  g_hl);
    cudaGetSymbolAddress((void**)&qh,  g_qh);  cudaGetSymbolAddress((void**)&ql,  g_ql);
    cudaGetSymbolAddress((void**)&sh,  g_sh);  cudaGetSymbolAddress((void**)&sl,  g_sl);
    cudaGetSymbolAddress((void**)&vth, g_vth); cudaGetSymbolAddress((void**)&vtl, g_vtl);
    cudaGetSymbolAddress((void**)&wh,  g_wh);  cudaGetSymbolAddress((void**)&wl,  g_wl);
    cudaGetSymbolAddress((void**)&o,   g_o);

    cudaFuncSetAttribute(mma_gemm<0, false, false, true >, cudaFuncAttributeMaxDynamicSharedMemorySize, SMEMB);
    cudaFuncSetAttribute(mma_gemm<1, false, false, true >, cudaFuncAttributeMaxDynamicSharedMemorySize, SMEMB);
    cudaFuncSetAttribute(mma_gemm<2, true,  false, true >, cudaFuncAttributeMaxDynamicSharedMemorySize, SMEMB);
    cudaFuncSetAttribute(mma_gemm<3, false, true,  false>, cudaFuncAttributeMaxDynamicSharedMemorySize, SMEMB);

    const float inv_scale = 1.0f / sqrtf((float)C_DIM * (float)T_SEQ);
    const long long CC = (long long)C_DIM * C_DIM;
    const long long MC = (long long)M_TOTAL * C_DIM;
    const long long TC = (long long)T_SEQ * C_DIM;
    const long long TT = (long long)T_SEQ * T_SEQ;

    // ---- prep: split x, transpose+split weights ----
    split_x_kernel<<<M_TOTAL * C_DIM / (256 * 4), 256>>>(
        (const float4*)x, (uint2*)xh, (uint2*)xl);
    dim3 tb(32, 8);
    wsplit_kernel<<<dim3(32, 32), tb>>>(W1q, wh + 0 * CC, wl + 0 * CC);
    wsplit_kernel<<<dim3(32, 32), tb>>>(W1k, wh + 1 * CC, wl + 1 * CC);
    wsplit_kernel<<<dim3(32, 32), tb>>>(W1v, wh + 2 * CC, wl + 2 * CC);
    wsplit_kernel<<<dim3(32, 32), tb>>>(W2q, wh + 3 * CC, wl + 3 * CC);
    wsplit_kernel<<<dim3(32, 32), tb>>>(W2k, wh + 4 * CC, wl + 4 * CC);
    wsplit_kernel<<<dim3(32, 32), tb>>>(W2v, wh + 5 * CC, wl + 5 * CC);

    // ---- MLP layer 1: h_z = GELU(x @ W1_z + b1_z), split output ----
    mma_gemm<0, false, false, true><<<dim3(C_DIM / BN, M_TOTAL / BM, 3), 256, SMEMB>>>(
        xh, xl, wh, wl, b1q, b1k, b1v, nullptr, hh, hl,
        C_DIM, C_DIM, C_DIM, C_DIM, 0, CC, MC, 0.0f);
    // ---- MLP layer 2: qkv_z = h_z @ W2_z + b2_z, split output ----
    mma_gemm<1, false, false, true><<<dim3(C_DIM / BN, M_TOTAL / BM, 3), 256, SMEMB>>>(
        hh, hl, wh + 3 * CC, wl + 3 * CC, b2q, b2k, b2v, nullptr, qh, ql,
        C_DIM, C_DIM, C_DIM, C_DIM, MC, CC, MC, 0.0f);

    // ---- V^T per batch (both planes) ----
    vtrans_kernel<<<dim3(C_DIM / 32, T_SEQ / 32, BATCH), tb>>>(
        qh + 2 * MC, ql + 2 * MC, vth, vtl);

    // ---- scores: S = mask(i>=j) * (q.k) * inv_scale, split output ----
    mma_gemm<2, true, false, true><<<dim3(T_SEQ / BN, T_SEQ / BM, BATCH), 256, SMEMB>>>(
        qh, ql, qh + MC, ql + MC, nullptr, nullptr, nullptr, nullptr, sh, sl,
        C_DIM, C_DIM, T_SEQ, C_DIM, TC, TC, TT, inv_scale);

    // ---- att: O = S @ V (causal K-limit), fp32 output ----
    mma_gemm<3, false, true, false><<<dim3(C_DIM / BN, T_SEQ / BM, BATCH), 256, SMEMB>>>(
        sh, sl, vth, vtl, nullptr, nullptr, nullptr, o, nullptr, nullptr,
        T_SEQ, T_SEQ, C_DIM, T_SEQ, TT, (long long)C_DIM * T_SEQ, TC, 0.0f);

    layernorm_kernel<<<M_TOTAL, 256>>>(o, ln_w, ln_b, out);
}

// round 7
// speedup vs baseline: 2.6850x; 1.0424x over previous
#include <cuda_runtime.h>
#include <cuda_bf16.h>
#include <math.h>
#include <stdint.h>

// ---------------- problem constants ----------------
#define C_DIM   1024
#define T_SEQ   2048
#define BATCH   8
#define M_TOTAL (BATCH * T_SEQ)       // 16384

// ---------------- tile config ----------------
#define BM 128
#define BN 128
#define BKF 32                         // k-values per chunk
#define ROWB 64                        // 32 bf16 per row, XOR-swizzled chunks
#define TILEB (128 * ROWB)             // 8192 B per plane tile
#define STAGEB (4 * TILEB)             // Ah,Al,Bh,Bl = 32768 B per stage
#define NSTAGE 3
#define SMEMB  (NSTAGE * STAGEB)       // 98304 B

// ---------------- scratch: split bf16 planes ----------------
__device__ __nv_bfloat16 g_xh [(size_t)M_TOTAL * C_DIM];
__device__ __nv_bfloat16 g_xl [(size_t)M_TOTAL * C_DIM];
__device__ __nv_bfloat16 g_hh [(size_t)3 * M_TOTAL * C_DIM];
__device__ __nv_bfloat16 g_hl [(size_t)3 * M_TOTAL * C_DIM];
__device__ __nv_bfloat16 g_qh [(size_t)3 * M_TOTAL * C_DIM];   // q|k|v planes
__device__ __nv_bfloat16 g_ql [(size_t)3 * M_TOTAL * C_DIM];
__device__ __nv_bfloat16 g_sh [(size_t)BATCH * T_SEQ * T_SEQ];
__device__ __nv_bfloat16 g_sl [(size_t)BATCH * T_SEQ * T_SEQ];
__device__ __nv_bfloat16 g_vth[(size_t)BATCH * C_DIM * T_SEQ];
__device__ __nv_bfloat16 g_vtl[(size_t)BATCH * C_DIM * T_SEQ];
__device__ __nv_bfloat16 g_wh [(size_t)6 * C_DIM * C_DIM];
__device__ __nv_bfloat16 g_wl [(size_t)6 * C_DIM * C_DIM];
__device__ float         g_o  [(size_t)M_TOTAL * C_DIM];

// ---------------- helpers ----------------
__device__ __forceinline__ uint32_t smem_u32(const void* p) {
    uint32_t a;
    asm("{ .reg .u64 t; cvta.to.shared.u64 t, %1; cvt.u32.u64 %0, t; }" : "=r"(a) : "l"(p));
    return a;
}
__device__ __forceinline__ void ldsm4(uint32_t* r, uint32_t addr) {
    asm volatile("ldmatrix.sync.aligned.m8n8.x4.shared.b16 {%0,%1,%2,%3}, [%4];"
                 : "=r"(r[0]), "=r"(r[1]), "=r"(r[2]), "=r"(r[3]) : "r"(addr));
}
__device__ __forceinline__ void mma16816(float* c, const uint32_t* a, uint32_t b0, uint32_t b1) {
    asm volatile("mma.sync.aligned.m16n8k16.row.col.f32.bf16.bf16.f32 "
                 "{%0,%1,%2,%3}, {%4,%5,%6,%7}, {%8,%9}, {%0,%1,%2,%3};"
                 : "+f"(c[0]), "+f"(c[1]), "+f"(c[2]), "+f"(c[3])
                 : "r"(a[0]), "r"(a[1]), "r"(a[2]), "r"(a[3]), "r"(b0), "r"(b1));
}
__device__ __forceinline__ void cpa16(uint32_t dst, const void* src) {
    asm volatile("cp.async.cg.shared.global [%0], [%1], 16;" :: "r"(dst), "l"(src));
}
__device__ __forceinline__ void cpa_commit() { asm volatile("cp.async.commit_group;" ::: "memory"); }
template <int N> __device__ __forceinline__ void cpa_wait() {
    asm volatile("cp.async.wait_group %0;" :: "n"(N) : "memory");
}
__device__ __forceinline__ float gelu_exact(float x) {
    return 0.5f * x * (1.0f + erff(x * 0.70710678118654752440f));
}
// (a,b) fp32 -> packed bf16x2 hi + lo
__device__ __forceinline__ void split2(float a, float b, uint32_t& hi, uint32_t& lo) {
    __nv_bfloat162 h = __floats2bfloat162_rn(a, b);
    __nv_bfloat162 l = __floats2bfloat162_rn(a - __bfloat162float(h.x),
                                             b - __bfloat162float(h.y));
    hi = *reinterpret_cast<uint32_t*>(&h);
    lo = *reinterpret_cast<uint32_t*>(&l);
}

// =====================================================================
// bf16x3 tensor-core GEMM on pre-split planes, 3-stage cp.async ring.
//   C[m,n] = epi( sum_k A[m,k]*B[n,k] ),  A=Ah+Al, B=Bh+Bl
//   EPI: 0 bias+GELU, 1 bias, 2 causal mask*scale, 3 plain
//   SKIP: skip CTA if bn > bm+127; CK: K limit = bm+128
//   OSPLIT: write split bf16 hi/lo planes instead of fp32
// MMA issue order: grouped by split-term (hh, hl, lh) across the 4
// accumulators of each ng block -> dependent-reuse distance 4, while the
// per-accumulator addition order stays (hh, hl, lh): bit-identical result.
// =====================================================================
template <int EPI, bool SKIP, bool CK, bool OSPLIT>
__global__ __launch_bounds__(256, 2)
void mma_gemm(const __nv_bfloat16* __restrict__ Ah, const __nv_bfloat16* __restrict__ Al,
              const __nv_bfloat16* __restrict__ Bh, const __nv_bfloat16* __restrict__ Bl,
              const float* __restrict__ b0, const float* __restrict__ b1,
              const float* __restrict__ b2,
              float* __restrict__ Co, __nv_bfloat16* __restrict__ Ch,
              __nv_bfloat16* __restrict__ Cl,
              int lda, int ldb, int ldc, int kdim,
              long long sA, long long sB, long long sC, float scale)
{
    const int bm = blockIdx.y * BM;
    const int bn = blockIdx.x * BN;
    if (SKIP && bn > bm + (BM - 1)) return;
    const int z = blockIdx.z;
    Ah += (size_t)z * sA; Al += (size_t)z * sA;
    Bh += (size_t)z * sB; Bl += (size_t)z * sB;
    if (OSPLIT) { Ch += (size_t)z * sC; Cl += (size_t)z * sC; }
    else        { Co += (size_t)z * sC; }
    const float* bias = (z == 0) ? b0 : ((z == 1) ? b1 : b2);

    extern __shared__ __align__(128) char smem[];
    const uint32_t sb = smem_u32(smem);
    const int tid = threadIdx.x, lane = tid & 31, wid = tid >> 5;
    const int wm = (wid >> 1) * 32;
    const int wn = (wid & 1) * 64;

    const int kend = CK ? (bm + BM) : kdim;
    const int NC = kend / BKF;

    // cp.async mapping: r0 = row, chunk c = tid&3, XOR-swizzled by (row>>1)&3
    const int r0 = tid >> 2;
    const int ck = tid & 3;
    const uint32_t sw0 = (uint32_t)((r0 >> 1) & 3);             // same for r0 and r0+64
    const uint32_t so0 = (uint32_t)r0 * ROWB + ((ck ^ sw0) * 16);
    const uint32_t so1 = so0 + 64u * ROWB;
    const int kc = ck * 8;                                       // bf16 elem offset

    auto issue = [&](int c) {
        const int k0 = c * BKF;
        const uint32_t stg = sb + (uint32_t)(c % NSTAGE) * STAGEB;
        cpa16(stg + 0 * TILEB + so0, Ah + (size_t)(bm + r0) * lda + k0 + kc);
        cpa16(stg + 1 * TILEB + so0, Al + (size_t)(bm + r0) * lda + k0 + kc);
        cpa16(stg + 2 * TILEB + so0, Bh + (size_t)(bn + r0) * ldb + k0 + kc);
        cpa16(stg + 3 * TILEB + so0, Bl + (size_t)(bn + r0) * ldb + k0 + kc);
        cpa16(stg + 0 * TILEB + so1, Ah + (size_t)(bm + r0 + 64) * lda + k0 + kc);
        cpa16(stg + 1 * TILEB + so1, Al + (size_t)(bm + r0 + 64) * lda + k0 + kc);
        cpa16(stg + 2 * TILEB + so1, Bh + (size_t)(bn + r0 + 64) * ldb + k0 + kc);
        cpa16(stg + 3 * TILEB + so1, Bl + (size_t)(bn + r0 + 64) * ldb + k0 + kc);
        cpa_commit();
    };

    float acc[2][8][4];
    #pragma unroll
    for (int mt = 0; mt < 2; mt++)
        #pragma unroll
        for (int nt = 0; nt < 8; nt++)
            #pragma unroll
            for (int e = 0; e < 4; e++) acc[mt][nt][e] = 0.0f;

    const uint32_t lrow = lane & 15;
    const uint32_t lc16 = (uint32_t)(lane >> 4);   // chunk sub-index from lane

    // precompute per-thread ldmatrix row offsets (swizzle depends on row)
    uint32_t aoff[2], boff[4];
    #pragma unroll
    for (int mt = 0; mt < 2; mt++) {
        const uint32_t row = (uint32_t)(wm + mt * 16) + lrow;
        aoff[mt] = row * ROWB + (((row >> 1) & 3) << 4);
    }
    #pragma unroll
    for (int ng = 0; ng < 4; ng++) {
        const uint32_t row = (uint32_t)(wn + ng * 16) + lrow;
        boff[ng] = row * ROWB + (((row >> 1) & 3) << 4);
    }

    issue(0);
    if (NC > 1) issue(1);

    for (int c = 0; c < NC; c++) {
        if (c + 1 < NC) cpa_wait<1>(); else cpa_wait<0>();
        __syncthreads();
        if (c + 2 < NC) issue(c + 2);    // safe: targets buffer consumed at c-1
        const uint32_t stg = sb + (uint32_t)(c % NSTAGE) * STAGEB;

        #pragma unroll
        for (int s = 0; s < 2; s++) {
            const uint32_t chunk = ((uint32_t)s * 2 + lc16) << 4;
            uint32_t ah[2][4], al[2][4];
            #pragma unroll
            for (int mt = 0; mt < 2; mt++) {
                const uint32_t ad = stg + (aoff[mt] ^ chunk);
                ldsm4(ah[mt], ad);
                ldsm4(al[mt], ad + 1 * TILEB);
            }
            #pragma unroll
            for (int ng = 0; ng < 4; ng++) {
                uint32_t bh[4], bl[4];
                const uint32_t bd = stg + (boff[ng] ^ chunk);
                ldsm4(bh, bd + 2 * TILEB);
                ldsm4(bl, bd + 3 * TILEB);
                // term 1: Ahi * Bhi  (4 independent accumulators)
                mma16816(acc[0][2 * ng],     ah[0], bh[0], bh[2]);
                mma16816(acc[0][2 * ng + 1], ah[0], bh[1], bh[3]);
                mma16816(acc[1][2 * ng],     ah[1], bh[0], bh[2]);
                mma16816(acc[1][2 * ng + 1], ah[1], bh[1], bh[3]);
                // term 2: Ahi * Blo
                mma16816(acc[0][2 * ng],     ah[0], bl[0], bl[2]);
                mma16816(acc[0][2 * ng + 1], ah[0], bl[1], bl[3]);
                mma16816(acc[1][2 * ng],     ah[1], bl[0], bl[2]);
                mma16816(acc[1][2 * ng + 1], ah[1], bl[1], bl[3]);
                // term 3: Alo * Bhi
                mma16816(acc[0][2 * ng],     al[0], bh[0], bh[2]);
                mma16816(acc[0][2 * ng + 1], al[0], bh[1], bh[3]);
                mma16816(acc[1][2 * ng],     al[1], bh[0], bh[2]);
                mma16816(acc[1][2 * ng + 1], al[1], bh[1], bh[3]);
            }
        }
    }

    // ---- epilogue ----
    const int erow = lane >> 2;
    const int ecol = (lane & 3) * 2;
    #pragma unroll
    for (int mt = 0; mt < 2; mt++) {
        #pragma unroll
        for (int nt = 0; nt < 8; nt++) {
            const int gr = bm + wm + mt * 16 + erow;
            const int gc = bn + wn + nt * 8 + ecol;
            float v0 = acc[mt][nt][0], v1 = acc[mt][nt][1];
            float v2 = acc[mt][nt][2], v3 = acc[mt][nt][3];
            if (EPI == 0) {
                const float bb0 = bias[gc], bb1 = bias[gc + 1];
                v0 = gelu_exact(v0 + bb0); v1 = gelu_exact(v1 + bb1);
                v2 = gelu_exact(v2 + bb0); v3 = gelu_exact(v3 + bb1);
            } else if (EPI == 1) {
                const float bb0 = bias[gc], bb1 = bias[gc + 1];
                v0 += bb0; v1 += bb1; v2 += bb0; v3 += bb1;
            } else if (EPI == 2) {
                v0 = (gr     >= gc    ) ? v0 * scale : 0.0f;
                v1 = (gr     >= gc + 1) ? v1 * scale : 0.0f;
                v2 = (gr + 8 >= gc    ) ? v2 * scale : 0.0f;
                v3 = (gr + 8 >= gc + 1) ? v3 * scale : 0.0f;
            }
            if (OSPLIT) {
                uint32_t h01, l01, h23, l23;
                split2(v0, v1, h01, l01);
                split2(v2, v3, h23, l23);
                *reinterpret_cast<uint32_t*>(Ch + (size_t)gr * ldc + gc)       = h01;
                *reinterpret_cast<uint32_t*>(Cl + (size_t)gr * ldc + gc)       = l01;
                *reinterpret_cast<uint32_t*>(Ch + (size_t)(gr + 8) * ldc + gc) = h23;
                *reinterpret_cast<uint32_t*>(Cl + (size_t)(gr + 8) * ldc + gc) = l23;
            } else {
                *reinterpret_cast<float2*>(Co + (size_t)gr * ldc + gc)       = make_float2(v0, v1);
                *reinterpret_cast<float2*>(Co + (size_t)(gr + 8) * ldc + gc) = make_float2(v2, v3);
            }
        }
    }
}

// =====================================================================
// x split: fp32 -> bf16 hi/lo planes
// =====================================================================
__global__ __launch_bounds__(256) void split_x_kernel(
    const float4* __restrict__ x, uint2* __restrict__ hi, uint2* __restrict__ lo)
{
    const int i = blockIdx.x * 256 + threadIdx.x;
    float4 v = x[i];
    uint32_t h01, l01, h23, l23;
    split2(v.x, v.y, h01, l01);
    split2(v.z, v.w, h23, l23);
    hi[i] = make_uint2(h01, h23);
    lo[i] = make_uint2(l01, l23);
}

// =====================================================================
// weight transpose+split: W[k,n] fp32 -> wh/wl [n,k] bf16
// =====================================================================
__global__ __launch_bounds__(256) void wsplit_kernel(
    const float* __restrict__ W, __nv_bfloat16* __restrict__ wh, __nv_bfloat16* __restrict__ wl)
{
    __shared__ float t[32][33];
    const int n0 = blockIdx.x * 32, k0 = blockIdx.y * 32;
    const int tx = threadIdx.x, ty = threadIdx.y;
    #pragma unroll
    for (int i = ty; i < 32; i += 8)
        t[i][tx] = W[(size_t)(k0 + i) * C_DIM + n0 + tx];
    __syncthreads();
    #pragma unroll
    for (int i = ty; i < 32; i += 8) {
        float v = t[tx][i];
        __nv_bfloat16 h = __float2bfloat16(v);
        wh[(size_t)(n0 + i) * C_DIM + k0 + tx] = h;
        wl[(size_t)(n0 + i) * C_DIM + k0 + tx] = __float2bfloat16(v - __bfloat162float(h));
    }
}

// =====================================================================
// V transpose (both planes): [T,C] -> [C,T], batched over z
// =====================================================================
__global__ __launch_bounds__(256) void vtrans_kernel(
    const __nv_bfloat16* __restrict__ vh, const __nv_bfloat16* __restrict__ vl,
    __nv_bfloat16* __restrict__ vth, __nv_bfloat16* __restrict__ vtl)
{
    __shared__ ushort th[32][33], tl[32][33];
    const int z = blockIdx.z;
    const ushort* ph = reinterpret_cast<const ushort*>(vh) + (size_t)z * T_SEQ * C_DIM;
    const ushort* pl = reinterpret_cast<const ushort*>(vl) + (size_t)z * T_SEQ * C_DIM;
    ushort* oh = reinterpret_cast<ushort*>(vth) + (size_t)z * C_DIM * T_SEQ;
    ushort* ol = reinterpret_cast<ushort*>(vtl) + (size_t)z * C_DIM * T_SEQ;
    const int c0 = blockIdx.x * 32, r0 = blockIdx.y * 32;
    const int tx = threadIdx.x, ty = threadIdx.y;
    #pragma unroll
    for (int i = ty; i < 32; i += 8) {
        th[i][tx] = ph[(size_t)(r0 + i) * C_DIM + c0 + tx];
        tl[i][tx] = pl[(size_t)(r0 + i) * C_DIM + c0 + tx];
    }
    __syncthreads();
    #pragma unroll
    for (int i = ty; i < 32; i += 8) {
        oh[(size_t)(c0 + i) * T_SEQ + r0 + tx] = th[tx][i];
        ol[(size_t)(c0 + i) * T_SEQ + r0 + tx] = tl[tx][i];
    }
}

// =====================================================================
// LayerNorm over last dim (C=1024), weight+bias, eps=1e-5
// =====================================================================
__global__ __launch_bounds__(256) void layernorm_kernel(
    const float* __restrict__ X, const float* __restrict__ w,
    const float* __restrict__ bia, float* __restrict__ out)
{
    const int row = blockIdx.x;
    const int tid = threadIdx.x;
    const float* xr = X + (size_t)row * C_DIM;

    float4 v = *reinterpret_cast<const float4*>(&xr[tid * 4]);
    float s  = v.x + v.y + v.z + v.w;
    float sq = v.x * v.x + v.y * v.y + v.z * v.z + v.w * v.w;
    #pragma unroll
    for (int off = 16; off > 0; off >>= 1) {
        s  += __shfl_xor_sync(0xffffffffu, s,  off);
        sq += __shfl_xor_sync(0xffffffffu, sq, off);
    }
    __shared__ float red_s[8], red_q[8];
    const int wid = tid >> 5;
    if ((tid & 31) == 0) { red_s[wid] = s; red_q[wid] = sq; }
    __syncthreads();
    __shared__ float mu_s, inv_s;
    if (tid == 0) {
        float ts = 0.f, tq = 0.f;
        #pragma unroll
        for (int i = 0; i < 8; i++) { ts += red_s[i]; tq += red_q[i]; }
        float mu  = ts * (1.0f / C_DIM);
        float var = tq * (1.0f / C_DIM) - mu * mu;
        mu_s = mu; inv_s = rsqrtf(var + 1e-5f);
    }
    __syncthreads();
    const float mu = mu_s, inv = inv_s;
    float4 wv = *reinterpret_cast<const float4*>(&w[tid * 4]);
    float4 bv = *reinterpret_cast<const float4*>(&bia[tid * 4]);
    float4 o;
    o.x = (v.x - mu) * inv * wv.x + bv.x;
    o.y = (v.y - mu) * inv * wv.y + bv.y;
    o.z = (v.z - mu) * inv * wv.z + bv.z;
    o.w = (v.w - mu) * inv * wv.w + bv.w;
    *reinterpret_cast<float4*>(&out[(size_t)row * C_DIM + tid * 4]) = o;
}

// =====================================================================
// launch
// =====================================================================
extern "C" void kernel_launch(void* const* d_in, const int* in_sizes, int n_in,
                              void* d_out, int out_size)
{
    (void)in_sizes; (void)n_in; (void)out_size;
    const float* x    = (const float*)d_in[0];
    const float* W1q  = (const float*)d_in[1];
    const float* b1q  = (const float*)d_in[2];
    const float* W2q  = (const float*)d_in[3];
    const float* b2q  = (const float*)d_in[4];
    const float* W1k  = (const float*)d_in[5];
    const float* b1k  = (const float*)d_in[6];
    const float* W2k  = (const float*)d_in[7];
    const float* b2k  = (const float*)d_in[8];
    const float* W1v  = (const float*)d_in[9];
    const float* b1v  = (const float*)d_in[10];
    const float* W2v  = (const float*)d_in[11];
    const float* b2v  = (const float*)d_in[12];
    const float* ln_w = (const float*)d_in[13];
    const float* ln_b = (const float*)d_in[14];
    float* out = (float*)d_out;

    __nv_bfloat16 *xh, *xl, *hh, *hl, *qh, *ql, *sh, *sl, *vth, *vtl, *wh, *wl;
    float* o;
    cudaGetSymbolAddress((void**)&xh,  g_xh);  cudaGetSymbolAddress((void**)&xl,  g_xl);
    cudaGetSymbolAddress((void**)&hh,  g_hh);  cudaGetSymbolAddress((void**)&hl,  g_hl);
    cudaGetSymbolAddress((void**)&qh,  g_qh);  cudaGetSymbolAddress((void**)&ql,  g_ql);
    cudaGetSymbolAddress((void**)&sh,  g_sh);  cudaGetSymbolAddress((void**)&sl,  g_sl);
    cudaGetSymbolAddress((void**)&vth, g_vth); cudaGetSymbolAddress((void**)&vtl, g_vtl);
    cudaGetSymbolAddress((void**)&wh,  g_wh);  cudaGetSymbolAddress((void**)&wl,  g_wl);
    cudaGetSymbolAddress((void**)&o,   g_o);

    cudaFuncSetAttribute(mma_gemm<0, false, false, true >, cudaFuncAttributeMaxDynamicSharedMemorySize, SMEMB);
    cudaFuncSetAttribute(mma_gemm<1, false, false, true >, cudaFuncAttributeMaxDynamicSharedMemorySize, SMEMB);
    cudaFuncSetAttribute(mma_gemm<2, true,  false, true >, cudaFuncAttributeMaxDynamicSharedMemorySize, SMEMB);
    cudaFuncSetAttribute(mma_gemm<3, false, true,  false>, cudaFuncAttributeMaxDynamicSharedMemorySize, SMEMB);

    const float inv_scale = 1.0f / sqrtf((float)C_DIM * (float)T_SEQ);
    const long long CC = (long long)C_DIM * C_DIM;
    const long long MC = (long long)M_TOTAL * C_DIM;
    const long long TC = (long long)T_SEQ * C_DIM;
    const long long TT = (long long)T_SEQ * T_SEQ;

    // ---- prep: split x, transpose+split weights ----
    split_x_kernel<<<M_TOTAL * C_DIM / (256 * 4), 256>>>(
        (const float4*)x, (uint2*)xh, (uint2*)xl);
    dim3 tb(32, 8);
    wsplit_kernel<<<dim3(32, 32), tb>>>(W1q, wh + 0 * CC, wl + 0 * CC);
    wsplit_kernel<<<dim3(32, 32), tb>>>(W1k, wh + 1 * CC, wl + 1 * CC);
    wsplit_kernel<<<dim3(32, 32), tb>>>(W1v, wh + 2 * CC, wl + 2 * CC);
    wsplit_kernel<<<dim3(32, 32), tb>>>(W2q, wh + 3 * CC, wl + 3 * CC);
    wsplit_kernel<<<dim3(32, 32), tb>>>(W2k, wh + 4 * CC, wl + 4 * CC);
    wsplit_kernel<<<dim3(32, 32), tb>>>(W2v, wh + 5 * CC, wl + 5 * CC);

    // ---- MLP layer 1: h_z = GELU(x @ W1_z + b1_z), split output ----
    mma_gemm<0, false, false, true><<<dim3(C_DIM / BN, M_TOTAL / BM, 3), 256, SMEMB>>>(
        xh, xl, wh, wl, b1q, b1k, b1v, nullptr, hh, hl,
        C_DIM, C_DIM, C_DIM, C_DIM, 0, CC, MC, 0.0f);
    // ---- MLP layer 2: qkv_z = h_z @ W2_z + b2_z, split output ----
    mma_gemm<1, false, false, true><<<dim3(C_DIM / BN, M_TOTAL / BM, 3), 256, SMEMB>>>(
        hh, hl, wh + 3 * CC, wl + 3 * CC, b2q, b2k, b2v, nullptr, qh, ql,
        C_DIM, C_DIM, C_DIM, C_DIM, MC, CC, MC, 0.0f);

    // ---- V^T per batch (both planes) ----
    vtrans_kernel<<<dim3(C_DIM / 32, T_SEQ / 32, BATCH), tb>>>(
        qh + 2 * MC, ql + 2 * MC, vth, vtl);

    // ---- scores: S = mask(i>=j) * (q.k) * inv_scale, split output ----
    mma_gemm<2, true, false, true><<<dim3(T_SEQ / BN, T_SEQ / BM, BATCH), 256, SMEMB>>>(
        qh, ql, qh + MC, ql + MC, nullptr, nullptr, nullptr, nullptr, sh, sl,
        C_DIM, C_DIM, T_SEQ, C_DIM, TC, TC, TT, inv_scale);

    // ---- att: O = S @ V (causal K-limit), fp32 output ----
    mma_gemm<3, false, true, false><<<dim3(C_DIM / BN, T_SEQ / BM, BATCH), 256, SMEMB>>>(
        sh, sl, vth, vtl, nullptr, nullptr, nullptr, o, nullptr, nullptr,
        T_SEQ, T_SEQ, C_DIM, T_SEQ, TT, (long long)C_DIM * T_SEQ, TC, 0.0f);

    layernorm_kernel<<<M_TOTAL, 256>>>(o, ln_w, ln_b, out);
}